// round 6
// baseline (speedup 1.0000x reference)
#include <cuda_runtime.h>
#include <cstdint>
#include <cstddef>

// Problem constants
#define BB 32
#define SS 8
#define TT 512
#define CC 128
#define HSZ 128

// Scratch (device globals; no runtime allocation allowed)
__device__ float g_M[CC * CC];                       // Wq @ Wk^T, tf32-rounded
__device__ float g_y[BB * TT * CC];                  // x @ M, tf32-rounded
__device__ float g_v[BB * TT * HSZ];                 // x @ Wv, tf32, COLUMN-PERMUTED: h -> (h&7)*16 + (h>>3)
__device__ float g_score[(size_t)BB * TT * TT];      // fp32 scores (33.5 MB)

__device__ __forceinline__ unsigned f2tf(float x) {
    unsigned u;
    asm("cvt.rna.tf32.f32 %0, %1;" : "=r"(u) : "f"(x));
    return u;
}
__device__ __forceinline__ float f2tf_f(float x) { return __uint_as_float(f2tf(x)); }

__device__ __forceinline__ void mma_tf32(float& c0, float& c1, float& c2, float& c3,
                                         unsigned a0, unsigned a1, unsigned a2, unsigned a3,
                                         unsigned b0, unsigned b1) {
    asm volatile(
        "mma.sync.aligned.m16n8k8.row.col.f32.tf32.tf32.f32 "
        "{%0,%1,%2,%3},{%4,%5,%6,%7},{%8,%9},{%0,%1,%2,%3};\n"
        : "+f"(c0), "+f"(c1), "+f"(c2), "+f"(c3)
        : "r"(a0), "r"(a1), "r"(a2), "r"(a3), "r"(b0), "r"(b1));
}

// ---------------------------------------------------------------------------
// K1: M = Wq @ Wk^T  (fp32 FFMA, rounded to tf32 on store)
// ---------------------------------------------------------------------------
__global__ void k_wqwk(const float* __restrict__ Wq, const float* __restrict__ Wk) {
    extern __shared__ float sm[];  // sWk[128][132]
    int tid = threadIdx.x;
    int c1 = blockIdx.x;
    for (int i = tid; i < CC * CC; i += 128) {
        sm[(i >> 7) * 132 + (i & 127)] = Wk[i];
    }
    __syncthreads();
    const float* wqr = Wq + c1 * CC;
    float acc = 0.f;
#pragma unroll 8
    for (int h = 0; h < CC; h++) acc += wqr[h] * sm[tid * 132 + h];
    g_M[c1 * CC + tid] = f2tf_f(acc);
}

// ---------------------------------------------------------------------------
// K2a: y = x @ M,  v = x @ Wv   (tf32 mma). v stored column-permuted.
// grid(B*T/64), block(128), dyn smem = 64*132*4
// ---------------------------------------------------------------------------
__global__ void __launch_bounds__(128) k_yv(const float* __restrict__ x,
                                            const float* __restrict__ Wv) {
    extern __shared__ float sm[];  // sx[64][132] tf32-rounded
    int tid = threadIdx.x;
    int row0 = blockIdx.x * 64;
    for (int f = tid; f < 64 * CC / 4; f += 128) {
        int r = f >> 5, c = (f & 31) * 4;
        float4 v4 = *reinterpret_cast<const float4*>(&x[(size_t)(row0 + r) * CC + c]);
        float4 o;
        o.x = f2tf_f(v4.x); o.y = f2tf_f(v4.y); o.z = f2tf_f(v4.z); o.w = f2tf_f(v4.w);
        *reinterpret_cast<float4*>(&sm[r * 132 + c]) = o;
    }
    __syncthreads();
    int lane = tid & 31, w = tid >> 5;
    int gid = lane >> 2, tig = lane & 3;
    int mrow = w * 16;
    for (int nt = 0; nt < 32; nt++) {
        bool isv = nt >= 16;
        const float* Bsrc = isv ? Wv : g_M;
        int nt8 = nt & 15;
        int n = nt8 * 8;
        float c0 = 0, c1 = 0, c2 = 0, c3 = 0;
#pragma unroll
        for (int kk = 0; kk < 16; kk++) {
            int k = kk * 8;
            unsigned a0 = __float_as_uint(sm[(mrow + gid) * 132 + k + tig]);
            unsigned a1 = __float_as_uint(sm[(mrow + gid + 8) * 132 + k + tig]);
            unsigned a2 = __float_as_uint(sm[(mrow + gid) * 132 + k + tig + 4]);
            unsigned a3 = __float_as_uint(sm[(mrow + gid + 8) * 132 + k + tig + 4]);
            float bv0 = Bsrc[(k + tig) * CC + n + gid];
            float bv1 = Bsrc[(k + tig + 4) * CC + n + gid];
            unsigned b0 = isv ? f2tf(bv0) : __float_as_uint(bv0);
            unsigned b1 = isv ? f2tf(bv1) : __float_as_uint(bv1);
            mma_tf32(c0, c1, c2, c3, a0, a1, a2, a3, b0, b1);
        }
        int r0 = row0 + mrow + gid;
        if (!isv) {
            g_y[(size_t)r0 * CC + n + 2 * tig]           = f2tf_f(c0);
            g_y[(size_t)r0 * CC + n + 2 * tig + 1]       = f2tf_f(c1);
            g_y[(size_t)(r0 + 8) * CC + n + 2 * tig]     = f2tf_f(c2);
            g_y[(size_t)(r0 + 8) * CC + n + 2 * tig + 1] = f2tf_f(c3);
        } else {
            // permuted store: col h -> (h&7)*16 + (h>>3)
            int col0 = 32 * tig + nt8;
            g_v[(size_t)r0 * HSZ + col0]            = f2tf_f(c0);
            g_v[(size_t)r0 * HSZ + col0 + 16]       = f2tf_f(c1);
            g_v[(size_t)(r0 + 8) * HSZ + col0]      = f2tf_f(c2);
            g_v[(size_t)(r0 + 8) * HSZ + col0 + 16] = f2tf_f(c3);
        }
    }
}

// ---------------------------------------------------------------------------
// K2b: score[b,t,u] = (y[b,t,:] . x[b,u,:]) * C^-0.5
// One u-chunk per block (stateless) -> single barrier, 8x blocks, low regs.
// grid(8, 8, 32) = (t_tile, u_chunk, b), block(128), dyn smem = 64*144*4
// ---------------------------------------------------------------------------
__global__ void __launch_bounds__(128) k_score(const float* __restrict__ x) {
    extern __shared__ float sxp[];  // [64][144] permuted tf32 x chunk
    int tid = threadIdx.x;
    int lane = tid & 31, w = tid >> 5, g = lane >> 2, t = lane & 3;
    int b = blockIdx.z;
    int t0 = blockIdx.x * 64;
    int u0 = blockIdx.y * 64;
    int mrow = w * 16;
    int R0 = t0 + mrow + g, R1 = R0 + 8;
    const float scl = 0.08838834764831843f;  // 128^-0.5

    // cooperative permuted load of x chunk (issue before A loads for overlap)
    for (int f = tid; f < 64 * CC / 4; f += 128) {
        int r = f >> 5, c4 = f & 31;
        float4 v4 = *reinterpret_cast<const float4*>(&x[(size_t)(b * TT + u0 + r) * CC + c4 * 4]);
        float* dst = &sxp[r * 144 + c4];  // element j goes to j*36 + c4
        dst[0]   = f2tf_f(v4.x);
        dst[36]  = f2tf_f(v4.y);
        dst[72]  = f2tf_f(v4.z);
        dst[108] = f2tf_f(v4.w);
    }

    // A fragments from g_y (already tf32)
    unsigned a0r[16], a1r[16], a2r[16], a3r[16];
    const float* y0 = g_y + (size_t)(b * TT + R0) * CC;
    const float* y1 = g_y + (size_t)(b * TT + R1) * CC;
#pragma unroll
    for (int kk = 0; kk < 16; kk++) {
        int c = 8 * kk + t;
        a0r[kk] = __float_as_uint(y0[c]);
        a1r[kk] = __float_as_uint(y1[c]);
        a2r[kk] = __float_as_uint(y0[c + 4]);
        a3r[kk] = __float_as_uint(y1[c + 4]);
    }
    __syncthreads();

#pragma unroll
    for (int nt = 0; nt < 8; nt++) {
        int brow = nt * 8 + g;
        const float4* bp = reinterpret_cast<const float4*>(&sxp[brow * 144 + t * 36]);
        float c0 = 0, c1 = 0, c2 = 0, c3 = 0;
#pragma unroll
        for (int j = 0; j < 8; j++) {
            float4 bq = bp[j];  // holds K pairs for kk=2j, 2j+1
            mma_tf32(c0, c1, c2, c3, a0r[2 * j], a1r[2 * j], a2r[2 * j], a3r[2 * j],
                     __float_as_uint(bq.x), __float_as_uint(bq.y));
            mma_tf32(c0, c1, c2, c3, a0r[2 * j + 1], a1r[2 * j + 1], a2r[2 * j + 1], a3r[2 * j + 1],
                     __float_as_uint(bq.z), __float_as_uint(bq.w));
        }
        float* d0 = g_score + ((size_t)b * TT + R0) * TT + u0 + nt * 8;
        float* d1 = g_score + ((size_t)b * TT + R1) * TT + u0 + nt * 8;
        *reinterpret_cast<float2*>(&d0[2 * t]) = make_float2(c0 * scl, c1 * scl);
        *reinterpret_cast<float2*>(&d1[2 * t]) = make_float2(c2 * scl, c3 * scl);
    }
}

// ---------------------------------------------------------------------------
// K3: flash softmax + P@V — ZERO shared memory, ZERO barriers.
// score & adj gathered directly into mma A-fragment registers;
// softmax state (m, l) register-resident per quad;
// V B-fragments read directly from permuted g_v via LDG.128 (L1-cached,
// reused 4x in-block and ~64x via L2 across blocks).
// grid(8, 8, 32) = (t_tile, s, b), block(128) = 4 warps x 16 rows
// ---------------------------------------------------------------------------
__global__ void __launch_bounds__(128) k_attn(const float* __restrict__ adj,
                                              float* __restrict__ out) {
    int tid = threadIdx.x, lane = tid & 31, w = tid >> 5;
    int g = lane >> 2, t = lane & 3;
    int t0 = blockIdx.x * 64, s = blockIdx.y, b = blockIdx.z;
    int mrow = w * 16;
    int R0 = t0 + mrow + g, R1 = R0 + 8;

    const float* srow0 = g_score + ((size_t)b * TT + R0) * TT;
    const float* srow1 = g_score + ((size_t)b * TT + R1) * TT;
    const float* arow0 = adj + (((size_t)b * SS + s) * TT + R0) * TT;
    const float* arow1 = adj + (((size_t)b * SS + s) * TT + R1) * TT;
    const float4* vb4 = reinterpret_cast<const float4*>(g_v + (size_t)b * TT * HSZ);

    float m0 = -1e30f, m1 = -1e30f, l0 = 0.f, l1 = 0.f;
    float acc[16][4];
#pragma unroll
    for (int nt = 0; nt < 16; nt++) {
        acc[nt][0] = 0.f; acc[nt][1] = 0.f; acc[nt][2] = 0.f; acc[nt][3] = 0.f;
    }

    for (int u0 = 0; u0 < TT; u0 += 64) {
        // gather w = score*adj directly in fragment layout (quad-contiguous 16B)
        float w0[8], w1[8], w2[8], w3[8];
#pragma unroll
        for (int kk = 0; kk < 8; kk++) {
            int c = u0 + 8 * kk + t;
            w0[kk] = srow0[c] * arow0[c];
            w1[kk] = srow1[c] * arow1[c];
            w2[kk] = srow0[c + 4] * arow0[c + 4];
            w3[kk] = srow1[c + 4] * arow1[c + 4];
        }
        // chunk row max (quad reduce)
        float mx0 = -1e30f, mx1 = -1e30f;
#pragma unroll
        for (int kk = 0; kk < 8; kk++) {
            mx0 = fmaxf(mx0, fmaxf(w0[kk], w2[kk]));
            mx1 = fmaxf(mx1, fmaxf(w1[kk], w3[kk]));
        }
        mx0 = fmaxf(mx0, __shfl_xor_sync(0xffffffffu, mx0, 1));
        mx0 = fmaxf(mx0, __shfl_xor_sync(0xffffffffu, mx0, 2));
        mx1 = fmaxf(mx1, __shfl_xor_sync(0xffffffffu, mx1, 1));
        mx1 = fmaxf(mx1, __shfl_xor_sync(0xffffffffu, mx1, 2));
        float m0n = fmaxf(m0, mx0), m1n = fmaxf(m1, mx1);
        float al0 = __expf(m0 - m0n), al1 = __expf(m1 - m1n);
        m0 = m0n; m1 = m1n;
        // exp + row sums
        float ps0 = 0.f, ps1 = 0.f;
#pragma unroll
        for (int kk = 0; kk < 8; kk++) {
            w0[kk] = __expf(w0[kk] - m0n); ps0 += w0[kk];
            w2[kk] = __expf(w2[kk] - m0n); ps0 += w2[kk];
            w1[kk] = __expf(w1[kk] - m1n); ps1 += w1[kk];
            w3[kk] = __expf(w3[kk] - m1n); ps1 += w3[kk];
        }
        ps0 += __shfl_xor_sync(0xffffffffu, ps0, 1);
        ps0 += __shfl_xor_sync(0xffffffffu, ps0, 2);
        ps1 += __shfl_xor_sync(0xffffffffu, ps1, 1);
        ps1 += __shfl_xor_sync(0xffffffffu, ps1, 2);
        l0 = l0 * al0 + ps0;
        l1 = l1 * al1 + ps1;
        // rescale accumulators
#pragma unroll
        for (int nt = 0; nt < 16; nt++) {
            acc[nt][0] *= al0; acc[nt][1] *= al0;
            acc[nt][2] *= al1; acc[nt][3] *= al1;
        }
        // P @ V : B-fragments straight from permuted g_v (L1-resident chunk)
#pragma unroll
        for (int kk = 0; kk < 8; kk++) {
            unsigned a0 = f2tf(w0[kk]);
            unsigned a1 = f2tf(w1[kk]);
            unsigned a2 = f2tf(w2[kk]);
            unsigned a3 = f2tf(w3[kk]);
            int row_lo = u0 + 8 * kk + t, row_hi = row_lo + 4;
            const float4* pl = &vb4[(size_t)row_lo * 32 + g * 4];
            const float4* ph = &vb4[(size_t)row_hi * 32 + g * 4];
#pragma unroll
            for (int j = 0; j < 4; j++) {
                float4 bl = pl[j];
                float4 bh = ph[j];
                int nt = 4 * j;
                mma_tf32(acc[nt][0], acc[nt][1], acc[nt][2], acc[nt][3],
                         a0, a1, a2, a3, __float_as_uint(bl.x), __float_as_uint(bh.x));
                mma_tf32(acc[nt + 1][0], acc[nt + 1][1], acc[nt + 1][2], acc[nt + 1][3],
                         a0, a1, a2, a3, __float_as_uint(bl.y), __float_as_uint(bh.y));
                mma_tf32(acc[nt + 2][0], acc[nt + 2][1], acc[nt + 2][2], acc[nt + 2][3],
                         a0, a1, a2, a3, __float_as_uint(bl.z), __float_as_uint(bh.z));
                mma_tf32(acc[nt + 3][0], acc[nt + 3][1], acc[nt + 3][2], acc[nt + 3][3],
                         a0, a1, a2, a3, __float_as_uint(bl.w), __float_as_uint(bh.w));
            }
        }
    }
    // epilogue
    float rl0 = 1.f / l0, rl1 = 1.f / l1;
    float* ob0 = out + (((size_t)b * SS + s) * TT + R0) * HSZ;
    float* ob1 = out + (((size_t)b * SS + s) * TT + R1) * HSZ;
#pragma unroll
    for (int nt = 0; nt < 16; nt++) {
        int c = 8 * nt + 2 * t;
        *reinterpret_cast<float2*>(&ob0[c]) = make_float2(acc[nt][0] * rl0, acc[nt][1] * rl0);
        *reinterpret_cast<float2*>(&ob1[c]) = make_float2(acc[nt][2] * rl1, acc[nt][3] * rl1);
    }
}

// ---------------------------------------------------------------------------
extern "C" void kernel_launch(void* const* d_in, const int* in_sizes, int n_in,
                              void* d_out, int out_size) {
    const float* x   = (const float*)d_in[0];
    const float* adj = (const float*)d_in[1];
    const float* Wq  = (const float*)d_in[2];
    const float* Wk  = (const float*)d_in[3];
    const float* Wv  = (const float*)d_in[4];
    float* out = (float*)d_out;

    const int smem_k1 = 128 * 132 * 4;     // 67584
    const int smem_k2a = 64 * 132 * 4;     // 33792
    const int smem_k2b = 64 * 144 * 4;     // 36864

    cudaFuncSetAttribute(k_wqwk, cudaFuncAttributeMaxDynamicSharedMemorySize, smem_k1);
    cudaFuncSetAttribute(k_yv, cudaFuncAttributeMaxDynamicSharedMemorySize, smem_k2a);
    cudaFuncSetAttribute(k_score, cudaFuncAttributeMaxDynamicSharedMemorySize, smem_k2b);

    k_wqwk<<<128, 128, smem_k1>>>(Wq, Wk);
    k_yv<<<(BB * TT) / 64, 128, smem_k2a>>>(x, Wv);
    k_score<<<dim3(TT / 64, TT / 64, BB), 128, smem_k2b>>>(x);
    k_attn<<<dim3(TT / 64, SS, BB), 128>>>(adj, out);
}

// round 7
// speedup vs baseline: 1.2990x; 1.2990x over previous
#include <cuda_runtime.h>
#include <cstdint>
#include <cstddef>

// Problem constants
#define BB 32
#define SS 8
#define TT 512
#define CC 128
#define HSZ 128

// Scratch (device globals; no runtime allocation allowed)
__device__ float g_M[CC * CC];                       // Wq @ Wk^T, tf32-rounded
__device__ float g_y[BB * TT * CC];                  // x @ M, tf32-rounded
__device__ float g_v[BB * TT * HSZ];                 // x @ Wv, tf32, COLUMN-PERMUTED: h -> (h&7)*16 + (h>>3)
__device__ float g_score[(size_t)BB * TT * TT];      // fp32 scores (33.5 MB)

__device__ __forceinline__ unsigned f2tf(float x) {
    unsigned u;
    asm("cvt.rna.tf32.f32 %0, %1;" : "=r"(u) : "f"(x));
    return u;
}
__device__ __forceinline__ float f2tf_f(float x) { return __uint_as_float(f2tf(x)); }

__device__ __forceinline__ void mma_tf32(float& c0, float& c1, float& c2, float& c3,
                                         unsigned a0, unsigned a1, unsigned a2, unsigned a3,
                                         unsigned b0, unsigned b1) {
    asm volatile(
        "mma.sync.aligned.m16n8k8.row.col.f32.tf32.tf32.f32 "
        "{%0,%1,%2,%3},{%4,%5,%6,%7},{%8,%9},{%0,%1,%2,%3};\n"
        : "+f"(c0), "+f"(c1), "+f"(c2), "+f"(c3)
        : "r"(a0), "r"(a1), "r"(a2), "r"(a3), "r"(b0), "r"(b1));
}

__device__ __forceinline__ void cp_async16(unsigned dst, const void* src) {
    asm volatile("cp.async.cg.shared.global [%0], [%1], 16;" :: "r"(dst), "l"(src) : "memory");
}

// ---------------------------------------------------------------------------
// K1: M = Wq @ Wk^T  (fp32 FFMA, rounded to tf32 on store)
// ---------------------------------------------------------------------------
__global__ void k_wqwk(const float* __restrict__ Wq, const float* __restrict__ Wk) {
    extern __shared__ float sm[];  // sWk[128][132]
    int tid = threadIdx.x;
    int c1 = blockIdx.x;
    for (int i = tid; i < CC * CC; i += 128) {
        sm[(i >> 7) * 132 + (i & 127)] = Wk[i];
    }
    __syncthreads();
    const float* wqr = Wq + c1 * CC;
    float acc = 0.f;
#pragma unroll 8
    for (int h = 0; h < CC; h++) acc += wqr[h] * sm[tid * 132 + h];
    g_M[c1 * CC + tid] = f2tf_f(acc);
}

// ---------------------------------------------------------------------------
// K2a: y = x @ M,  v = x @ Wv   (tf32 mma). v stored column-permuted.
// grid(B*T/64), block(128), dyn smem = 64*132*4
// ---------------------------------------------------------------------------
__global__ void __launch_bounds__(128) k_yv(const float* __restrict__ x,
                                            const float* __restrict__ Wv) {
    extern __shared__ float sm[];  // sx[64][132] tf32-rounded
    int tid = threadIdx.x;
    int row0 = blockIdx.x * 64;
    for (int f = tid; f < 64 * CC / 4; f += 128) {
        int r = f >> 5, c = (f & 31) * 4;
        float4 v4 = *reinterpret_cast<const float4*>(&x[(size_t)(row0 + r) * CC + c]);
        float4 o;
        o.x = f2tf_f(v4.x); o.y = f2tf_f(v4.y); o.z = f2tf_f(v4.z); o.w = f2tf_f(v4.w);
        *reinterpret_cast<float4*>(&sm[r * 132 + c]) = o;
    }
    __syncthreads();
    int lane = tid & 31, w = tid >> 5;
    int gid = lane >> 2, tig = lane & 3;
    int mrow = w * 16;
    for (int nt = 0; nt < 32; nt++) {
        bool isv = nt >= 16;
        const float* Bsrc = isv ? Wv : g_M;
        int nt8 = nt & 15;
        int n = nt8 * 8;
        float c0 = 0, c1 = 0, c2 = 0, c3 = 0;
#pragma unroll
        for (int kk = 0; kk < 16; kk++) {
            int k = kk * 8;
            unsigned a0 = __float_as_uint(sm[(mrow + gid) * 132 + k + tig]);
            unsigned a1 = __float_as_uint(sm[(mrow + gid + 8) * 132 + k + tig]);
            unsigned a2 = __float_as_uint(sm[(mrow + gid) * 132 + k + tig + 4]);
            unsigned a3 = __float_as_uint(sm[(mrow + gid + 8) * 132 + k + tig + 4]);
            float bv0 = Bsrc[(k + tig) * CC + n + gid];
            float bv1 = Bsrc[(k + tig + 4) * CC + n + gid];
            unsigned b0 = isv ? f2tf(bv0) : __float_as_uint(bv0);
            unsigned b1 = isv ? f2tf(bv1) : __float_as_uint(bv1);
            mma_tf32(c0, c1, c2, c3, a0, a1, a2, a3, b0, b1);
        }
        int r0 = row0 + mrow + gid;
        if (!isv) {
            g_y[(size_t)r0 * CC + n + 2 * tig]           = f2tf_f(c0);
            g_y[(size_t)r0 * CC + n + 2 * tig + 1]       = f2tf_f(c1);
            g_y[(size_t)(r0 + 8) * CC + n + 2 * tig]     = f2tf_f(c2);
            g_y[(size_t)(r0 + 8) * CC + n + 2 * tig + 1] = f2tf_f(c3);
        } else {
            // permuted store: col h -> (h&7)*16 + (h>>3)
            int col0 = 32 * tig + nt8;
            g_v[(size_t)r0 * HSZ + col0]            = f2tf_f(c0);
            g_v[(size_t)r0 * HSZ + col0 + 16]       = f2tf_f(c1);
            g_v[(size_t)(r0 + 8) * HSZ + col0]      = f2tf_f(c2);
            g_v[(size_t)(r0 + 8) * HSZ + col0 + 16] = f2tf_f(c3);
        }
    }
}

// ---------------------------------------------------------------------------
// K2b: score[b,t,u] = (y[b,t,:] . x[b,u,:]) * C^-0.5
// One u-chunk per block (stateless) -> single barrier, low regs.
// grid(8, 8, 32) = (t_tile, u_chunk, b), block(128), dyn smem = 64*144*4
// ---------------------------------------------------------------------------
__global__ void __launch_bounds__(128) k_score(const float* __restrict__ x) {
    extern __shared__ float sxp[];  // [64][144] permuted tf32 x chunk
    int tid = threadIdx.x;
    int lane = tid & 31, w = tid >> 5, g = lane >> 2, t = lane & 3;
    int b = blockIdx.z;
    int t0 = blockIdx.x * 64;
    int u0 = blockIdx.y * 64;
    int mrow = w * 16;
    int R0 = t0 + mrow + g, R1 = R0 + 8;
    const float scl = 0.08838834764831843f;  // 128^-0.5

    // cooperative permuted load of x chunk (issue before A loads for overlap)
    for (int f = tid; f < 64 * CC / 4; f += 128) {
        int r = f >> 5, c4 = f & 31;
        float4 v4 = *reinterpret_cast<const float4*>(&x[(size_t)(b * TT + u0 + r) * CC + c4 * 4]);
        float* dst = &sxp[r * 144 + c4];  // element j goes to j*36 + c4
        dst[0]   = f2tf_f(v4.x);
        dst[36]  = f2tf_f(v4.y);
        dst[72]  = f2tf_f(v4.z);
        dst[108] = f2tf_f(v4.w);
    }

    // A fragments from g_y (already tf32)
    unsigned a0r[16], a1r[16], a2r[16], a3r[16];
    const float* y0 = g_y + (size_t)(b * TT + R0) * CC;
    const float* y1 = g_y + (size_t)(b * TT + R1) * CC;
#pragma unroll
    for (int kk = 0; kk < 16; kk++) {
        int c = 8 * kk + t;
        a0r[kk] = __float_as_uint(y0[c]);
        a1r[kk] = __float_as_uint(y1[c]);
        a2r[kk] = __float_as_uint(y0[c + 4]);
        a3r[kk] = __float_as_uint(y1[c + 4]);
    }
    __syncthreads();

#pragma unroll
    for (int nt = 0; nt < 8; nt++) {
        int brow = nt * 8 + g;
        const float4* bp = reinterpret_cast<const float4*>(&sxp[brow * 144 + t * 36]);
        float c0 = 0, c1 = 0, c2 = 0, c3 = 0;
#pragma unroll
        for (int j = 0; j < 8; j++) {
            float4 bq = bp[j];  // holds K pairs for kk=2j, 2j+1
            mma_tf32(c0, c1, c2, c3, a0r[2 * j], a1r[2 * j], a2r[2 * j], a3r[2 * j],
                     __float_as_uint(bq.x), __float_as_uint(bq.y));
            mma_tf32(c0, c1, c2, c3, a0r[2 * j + 1], a1r[2 * j + 1], a2r[2 * j + 1], a3r[2 * j + 1],
                     __float_as_uint(bq.z), __float_as_uint(bq.w));
        }
        float* d0 = g_score + ((size_t)b * TT + R0) * TT + u0 + nt * 8;
        float* d1 = g_score + ((size_t)b * TT + R1) * TT + u0 + nt * 8;
        *reinterpret_cast<float2*>(&d0[2 * t]) = make_float2(c0 * scl, c1 * scl);
        *reinterpret_cast<float2*>(&d1[2 * t]) = make_float2(c2 * scl, c3 * scl);
    }
}

// ---------------------------------------------------------------------------
// K3: flash-style softmax (no max subtraction; scores are O(10), exp is safe)
// + P@V with tf32 mma.
// block 256 = 8 warps; t-tile 128 rows; warp = 32 rows x 64 cols
//   warp w: row-group (w&3)*32, n-half (w>>2)*64.
// K-axis reindex: mma slice kk uses u = 8t + {kk, 4+kk}; lane's score/adj
//   gather is 2 contiguous float4 per row per 32-u sub-chunk.
// V smem rows permuted: chunk row u stored at rho = (u&32) + (u&7)*4 + ((u>>3)&3)
//   -> B-fragment LDS.128 rows are consecutive in t => conflict-free.
// cp.async double-buffered V chunks.
// grid(4, 8, 32) = (t_tile, s, b); dyn smem = 2*64*132*4 = 67584
// ---------------------------------------------------------------------------
__global__ void __launch_bounds__(256, 1) k_attn(const float* __restrict__ adj,
                                                 float* __restrict__ out) {
    extern __shared__ float sv[];
    int tid = threadIdx.x, lane = tid & 31, w8 = tid >> 5;
    int g = lane >> 2, t = lane & 3;
    int rg = w8 & 3, nh = w8 >> 2;
    int s = blockIdx.y, b = blockIdx.z;
    int tbase = blockIdx.x * 128 + rg * 32;
    int r0 = tbase + g, r1 = r0 + 8, r2 = r0 + 16, r3 = r0 + 24;

    const float* s0 = g_score + ((size_t)b * TT + r0) * TT;
    const float* s1 = g_score + ((size_t)b * TT + r1) * TT;
    const float* s2 = g_score + ((size_t)b * TT + r2) * TT;
    const float* s3 = g_score + ((size_t)b * TT + r3) * TT;
    const float* a0p = adj + (((size_t)b * SS + s) * TT + r0) * TT;
    const float* a1p = adj + (((size_t)b * SS + s) * TT + r1) * TT;
    const float* a2p = adj + (((size_t)b * SS + s) * TT + r2) * TT;
    const float* a3p = adj + (((size_t)b * SS + s) * TT + r3) * TT;
    const float4* gv4 = reinterpret_cast<const float4*>(g_v + (size_t)b * TT * HSZ);
    const float4* sv4 = reinterpret_cast<const float4*>(sv);
    unsigned svb = (unsigned)__cvta_generic_to_shared(sv);

    float acc0[8][4], acc1[8][4];
#pragma unroll
    for (int e = 0; e < 8; e++) {
        acc0[e][0] = 0.f; acc0[e][1] = 0.f; acc0[e][2] = 0.f; acc0[e][3] = 0.f;
        acc1[e][0] = 0.f; acc1[e][1] = 0.f; acc1[e][2] = 0.f; acc1[e][3] = 0.f;
    }
    float l0 = 0.f, l1 = 0.f, l2 = 0.f, l3 = 0.f;

    // prologue: chunk 0 -> buffer 0
    for (int f = tid; f < 2048; f += 256) {
        int u = f >> 5, c16 = f & 31;
        int rho = (u & 32) + ((u & 7) << 2) + ((u >> 3) & 3);
        cp_async16(svb + (unsigned)((rho * 33 + c16) << 4), gv4 + (size_t)u * 32 + c16);
    }
    asm volatile("cp.async.commit_group;" ::: "memory");

    for (int ch = 0; ch < 8; ch++) {
        int u0 = ch * 64;
        if (ch < 7) {
            unsigned boff = (unsigned)(((ch + 1) & 1) * 33792);
            int ubase = u0 + 64;
            for (int f = tid; f < 2048; f += 256) {
                int u = f >> 5, c16 = f & 31;
                int rho = (u & 32) + ((u & 7) << 2) + ((u >> 3) & 3);
                cp_async16(svb + boff + (unsigned)((rho * 33 + c16) << 4),
                           gv4 + (size_t)(ubase + u) * 32 + c16);
            }
            asm volatile("cp.async.commit_group;" ::: "memory");
            asm volatile("cp.async.wait_group 1;" ::: "memory");
        } else {
            asm volatile("cp.async.wait_group 0;" ::: "memory");
        }
        __syncthreads();
        const float4* vb = sv4 + (ch & 1) * 2112;

#pragma unroll
        for (int sh = 0; sh < 2; sh++) {
            int cb = u0 + sh * 32 + 8 * t;
            float w0[8], w1[8], w2[8], w3[8];
            {
                float4 xa = *reinterpret_cast<const float4*>(s0 + cb);
                float4 xb = *reinterpret_cast<const float4*>(s0 + cb + 4);
                float4 ya = *reinterpret_cast<const float4*>(a0p + cb);
                float4 yb = *reinterpret_cast<const float4*>(a0p + cb + 4);
                w0[0] = __expf(xa.x * ya.x); w0[1] = __expf(xa.y * ya.y);
                w0[2] = __expf(xa.z * ya.z); w0[3] = __expf(xa.w * ya.w);
                w0[4] = __expf(xb.x * yb.x); w0[5] = __expf(xb.y * yb.y);
                w0[6] = __expf(xb.z * yb.z); w0[7] = __expf(xb.w * yb.w);
                l0 += ((w0[0] + w0[1]) + (w0[2] + w0[3])) + ((w0[4] + w0[5]) + (w0[6] + w0[7]));
            }
            {
                float4 xa = *reinterpret_cast<const float4*>(s1 + cb);
                float4 xb = *reinterpret_cast<const float4*>(s1 + cb + 4);
                float4 ya = *reinterpret_cast<const float4*>(a1p + cb);
                float4 yb = *reinterpret_cast<const float4*>(a1p + cb + 4);
                w1[0] = __expf(xa.x * ya.x); w1[1] = __expf(xa.y * ya.y);
                w1[2] = __expf(xa.z * ya.z); w1[3] = __expf(xa.w * ya.w);
                w1[4] = __expf(xb.x * yb.x); w1[5] = __expf(xb.y * yb.y);
                w1[6] = __expf(xb.z * yb.z); w1[7] = __expf(xb.w * yb.w);
                l1 += ((w1[0] + w1[1]) + (w1[2] + w1[3])) + ((w1[4] + w1[5]) + (w1[6] + w1[7]));
            }
            {
                float4 xa = *reinterpret_cast<const float4*>(s2 + cb);
                float4 xb = *reinterpret_cast<const float4*>(s2 + cb + 4);
                float4 ya = *reinterpret_cast<const float4*>(a2p + cb);
                float4 yb = *reinterpret_cast<const float4*>(a2p + cb + 4);
                w2[0] = __expf(xa.x * ya.x); w2[1] = __expf(xa.y * ya.y);
                w2[2] = __expf(xa.z * ya.z); w2[3] = __expf(xa.w * ya.w);
                w2[4] = __expf(xb.x * yb.x); w2[5] = __expf(xb.y * yb.y);
                w2[6] = __expf(xb.z * yb.z); w2[7] = __expf(xb.w * yb.w);
                l2 += ((w2[0] + w2[1]) + (w2[2] + w2[3])) + ((w2[4] + w2[5]) + (w2[6] + w2[7]));
            }
            {
                float4 xa = *reinterpret_cast<const float4*>(s3 + cb);
                float4 xb = *reinterpret_cast<const float4*>(s3 + cb + 4);
                float4 ya = *reinterpret_cast<const float4*>(a3p + cb);
                float4 yb = *reinterpret_cast<const float4*>(a3p + cb + 4);
                w3[0] = __expf(xa.x * ya.x); w3[1] = __expf(xa.y * ya.y);
                w3[2] = __expf(xa.z * ya.z); w3[3] = __expf(xa.w * ya.w);
                w3[4] = __expf(xb.x * yb.x); w3[5] = __expf(xb.y * yb.y);
                w3[6] = __expf(xb.z * yb.z); w3[7] = __expf(xb.w * yb.w);
                l3 += ((w3[0] + w3[1]) + (w3[2] + w3[3])) + ((w3[4] + w3[5]) + (w3[6] + w3[7]));
            }
#pragma unroll
            for (int kk = 0; kk < 4; kk++) {
                int rlo = sh * 32 + kk * 4 + t;
                const float4* plo = vb + rlo * 33 + 4 * g + 2 * nh;
                const float4* phi = plo + 16 * 33;
                float4 bl0 = plo[0], bl1 = plo[1];
                float4 bh0 = phi[0], bh1 = phi[1];
                unsigned p00 = f2tf(w0[kk]), p01 = f2tf(w1[kk]);
                unsigned p02 = f2tf(w0[4 + kk]), p03 = f2tf(w1[4 + kk]);
                unsigned p10 = f2tf(w2[kk]), p11 = f2tf(w3[kk]);
                unsigned p12 = f2tf(w2[4 + kk]), p13 = f2tf(w3[4 + kk]);
                mma_tf32(acc0[0][0], acc0[0][1], acc0[0][2], acc0[0][3], p00, p01, p02, p03,
                         __float_as_uint(bl0.x), __float_as_uint(bh0.x));
                mma_tf32(acc0[1][0], acc0[1][1], acc0[1][2], acc0[1][3], p00, p01, p02, p03,
                         __float_as_uint(bl0.y), __float_as_uint(bh0.y));
                mma_tf32(acc0[2][0], acc0[2][1], acc0[2][2], acc0[2][3], p00, p01, p02, p03,
                         __float_as_uint(bl0.z), __float_as_uint(bh0.z));
                mma_tf32(acc0[3][0], acc0[3][1], acc0[3][2], acc0[3][3], p00, p01, p02, p03,
                         __float_as_uint(bl0.w), __float_as_uint(bh0.w));
                mma_tf32(acc0[4][0], acc0[4][1], acc0[4][2], acc0[4][3], p00, p01, p02, p03,
                         __float_as_uint(bl1.x), __float_as_uint(bh1.x));
                mma_tf32(acc0[5][0], acc0[5][1], acc0[5][2], acc0[5][3], p00, p01, p02, p03,
                         __float_as_uint(bl1.y), __float_as_uint(bh1.y));
                mma_tf32(acc0[6][0], acc0[6][1], acc0[6][2], acc0[6][3], p00, p01, p02, p03,
                         __float_as_uint(bl1.z), __float_as_uint(bh1.z));
                mma_tf32(acc0[7][0], acc0[7][1], acc0[7][2], acc0[7][3], p00, p01, p02, p03,
                         __float_as_uint(bl1.w), __float_as_uint(bh1.w));
                mma_tf32(acc1[0][0], acc1[0][1], acc1[0][2], acc1[0][3], p10, p11, p12, p13,
                         __float_as_uint(bl0.x), __float_as_uint(bh0.x));
                mma_tf32(acc1[1][0], acc1[1][1], acc1[1][2], acc1[1][3], p10, p11, p12, p13,
                         __float_as_uint(bl0.y), __float_as_uint(bh0.y));
                mma_tf32(acc1[2][0], acc1[2][1], acc1[2][2], acc1[2][3], p10, p11, p12, p13,
                         __float_as_uint(bl0.z), __float_as_uint(bh0.z));
                mma_tf32(acc1[3][0], acc1[3][1], acc1[3][2], acc1[3][3], p10, p11, p12, p13,
                         __float_as_uint(bl0.w), __float_as_uint(bh0.w));
                mma_tf32(acc1[4][0], acc1[4][1], acc1[4][2], acc1[4][3], p10, p11, p12, p13,
                         __float_as_uint(bl1.x), __float_as_uint(bh1.x));
                mma_tf32(acc1[5][0], acc1[5][1], acc1[5][2], acc1[5][3], p10, p11, p12, p13,
                         __float_as_uint(bl1.y), __float_as_uint(bh1.y));
                mma_tf32(acc1[6][0], acc1[6][1], acc1[6][2], acc1[6][3], p10, p11, p12, p13,
                         __float_as_uint(bl1.z), __float_as_uint(bh1.z));
                mma_tf32(acc1[7][0], acc1[7][1], acc1[7][2], acc1[7][3], p10, p11, p12, p13,
                         __float_as_uint(bl1.w), __float_as_uint(bh1.w));
            }
        }
        __syncthreads();
    }

    // epilogue: quad-reduce row sums (over t lanes), normalize, store
    l0 += __shfl_xor_sync(0xffffffffu, l0, 1); l0 += __shfl_xor_sync(0xffffffffu, l0, 2);
    l1 += __shfl_xor_sync(0xffffffffu, l1, 1); l1 += __shfl_xor_sync(0xffffffffu, l1, 2);
    l2 += __shfl_xor_sync(0xffffffffu, l2, 1); l2 += __shfl_xor_sync(0xffffffffu, l2, 2);
    l3 += __shfl_xor_sync(0xffffffffu, l3, 1); l3 += __shfl_xor_sync(0xffffffffu, l3, 2);
    float rl0 = 1.f / l0, rl1 = 1.f / l1, rl2 = 1.f / l2, rl3 = 1.f / l3;

    float* ob0 = out + (((size_t)b * SS + s) * TT + r0) * HSZ + 64 * nh;
    float* ob1 = out + (((size_t)b * SS + s) * TT + r1) * HSZ + 64 * nh;
    float* ob2 = out + (((size_t)b * SS + s) * TT + r2) * HSZ + 64 * nh;
    float* ob3 = out + (((size_t)b * SS + s) * TT + r3) * HSZ + 64 * nh;
#pragma unroll
    for (int e = 0; e < 8; e++) {
        int c = 8 * e + 2 * t;
        *reinterpret_cast<float2*>(&ob0[c]) = make_float2(acc0[e][0] * rl0, acc0[e][1] * rl0);
        *reinterpret_cast<float2*>(&ob1[c]) = make_float2(acc0[e][2] * rl1, acc0[e][3] * rl1);
        *reinterpret_cast<float2*>(&ob2[c]) = make_float2(acc1[e][0] * rl2, acc1[e][1] * rl2);
        *reinterpret_cast<float2*>(&ob3[c]) = make_float2(acc1[e][2] * rl3, acc1[e][3] * rl3);
    }
}

// ---------------------------------------------------------------------------
extern "C" void kernel_launch(void* const* d_in, const int* in_sizes, int n_in,
                              void* d_out, int out_size) {
    const float* x   = (const float*)d_in[0];
    const float* adj = (const float*)d_in[1];
    const float* Wq  = (const float*)d_in[2];
    const float* Wk  = (const float*)d_in[3];
    const float* Wv  = (const float*)d_in[4];
    float* out = (float*)d_out;

    const int smem_k1 = 128 * 132 * 4;     // 67584
    const int smem_k2a = 64 * 132 * 4;     // 33792
    const int smem_k2b = 64 * 144 * 4;     // 36864
    const int smem_k3 = 2 * 64 * 132 * 4;  // 67584 (double-buffered V)

    cudaFuncSetAttribute(k_wqwk, cudaFuncAttributeMaxDynamicSharedMemorySize, smem_k1);
    cudaFuncSetAttribute(k_yv, cudaFuncAttributeMaxDynamicSharedMemorySize, smem_k2a);
    cudaFuncSetAttribute(k_score, cudaFuncAttributeMaxDynamicSharedMemorySize, smem_k2b);
    cudaFuncSetAttribute(k_attn, cudaFuncAttributeMaxDynamicSharedMemorySize, smem_k3);

    k_wqwk<<<128, 128, smem_k1>>>(Wq, Wk);
    k_yv<<<(BB * TT) / 64, 128, smem_k2a>>>(x, Wv);
    k_score<<<dim3(TT / 64, TT / 64, BB), 128, smem_k2b>>>(x);
    k_attn<<<dim3(TT / 128, SS, BB), 256, smem_k3>>>(adj, out);
}

// round 9
// speedup vs baseline: 1.6811x; 1.2942x over previous
#include <cuda_runtime.h>
#include <cstdint>
#include <cstddef>

// Problem constants
#define BB 32
#define SS 8
#define TT 512
#define CC 128
#define HSZ 128

// Scratch (device globals; no runtime allocation allowed)
__device__ float g_M[CC * CC];                       // Wq @ Wk^T, tf32-rounded
__device__ float g_y[BB * TT * CC];                  // x @ M, tf32-rounded
__device__ float g_v[BB * TT * HSZ];                 // x @ Wv, tf32, COLUMN-PERMUTED: h -> (h&7)*16 + (h>>3)
__device__ float g_score[(size_t)BB * TT * TT];      // fp32 scores (33.5 MB)

__device__ __forceinline__ unsigned f2tf(float x) {
    unsigned u;
    asm("cvt.rna.tf32.f32 %0, %1;" : "=r"(u) : "f"(x));
    return u;
}
__device__ __forceinline__ float f2tf_f(float x) { return __uint_as_float(f2tf(x)); }

__device__ __forceinline__ void mma_tf32(float& c0, float& c1, float& c2, float& c3,
                                         unsigned a0, unsigned a1, unsigned a2, unsigned a3,
                                         unsigned b0, unsigned b1) {
    asm volatile(
        "mma.sync.aligned.m16n8k8.row.col.f32.tf32.tf32.f32 "
        "{%0,%1,%2,%3},{%4,%5,%6,%7},{%8,%9},{%0,%1,%2,%3};\n"
        : "+f"(c0), "+f"(c1), "+f"(c2), "+f"(c3)
        : "r"(a0), "r"(a1), "r"(a2), "r"(a3), "r"(b0), "r"(b1));
}

__device__ __forceinline__ void cp_async16(unsigned dst, const void* src) {
    asm volatile("cp.async.cg.shared.global [%0], [%1], 16;" :: "r"(dst), "l"(src) : "memory");
}

// ---------------------------------------------------------------------------
// K1: M = Wq @ Wk^T  (fp32 FFMA, rounded to tf32 on store)
// ---------------------------------------------------------------------------
__global__ void k_wqwk(const float* __restrict__ Wq, const float* __restrict__ Wk) {
    extern __shared__ float sm[];  // sWk[128][132]
    int tid = threadIdx.x;
    int c1 = blockIdx.x;
    for (int i = tid; i < CC * CC; i += 128) {
        sm[(i >> 7) * 132 + (i & 127)] = Wk[i];
    }
    __syncthreads();
    const float* wqr = Wq + c1 * CC;
    float acc = 0.f;
#pragma unroll 8
    for (int h = 0; h < CC; h++) acc += wqr[h] * sm[tid * 132 + h];
    g_M[c1 * CC + tid] = f2tf_f(acc);
}

// ---------------------------------------------------------------------------
// K2a: y = x @ M,  v = x @ Wv   (tf32 mma). v stored column-permuted.
// grid(B*T/64), block(128), dyn smem = 64*132*4
// ---------------------------------------------------------------------------
__global__ void __launch_bounds__(128) k_yv(const float* __restrict__ x,
                                            const float* __restrict__ Wv) {
    extern __shared__ float sm[];  // sx[64][132] tf32-rounded
    int tid = threadIdx.x;
    int row0 = blockIdx.x * 64;
    for (int f = tid; f < 64 * CC / 4; f += 128) {
        int r = f >> 5, c = (f & 31) * 4;
        float4 v4 = *reinterpret_cast<const float4*>(&x[(size_t)(row0 + r) * CC + c]);
        float4 o;
        o.x = f2tf_f(v4.x); o.y = f2tf_f(v4.y); o.z = f2tf_f(v4.z); o.w = f2tf_f(v4.w);
        *reinterpret_cast<float4*>(&sm[r * 132 + c]) = o;
    }
    __syncthreads();
    int lane = tid & 31, w = tid >> 5;
    int gid = lane >> 2, tig = lane & 3;
    int mrow = w * 16;
    for (int nt = 0; nt < 32; nt++) {
        bool isv = nt >= 16;
        const float* Bsrc = isv ? Wv : g_M;
        int nt8 = nt & 15;
        int n = nt8 * 8;
        float c0 = 0, c1 = 0, c2 = 0, c3 = 0;
#pragma unroll
        for (int kk = 0; kk < 16; kk++) {
            int k = kk * 8;
            unsigned a0 = __float_as_uint(sm[(mrow + gid) * 132 + k + tig]);
            unsigned a1 = __float_as_uint(sm[(mrow + gid + 8) * 132 + k + tig]);
            unsigned a2 = __float_as_uint(sm[(mrow + gid) * 132 + k + tig + 4]);
            unsigned a3 = __float_as_uint(sm[(mrow + gid + 8) * 132 + k + tig + 4]);
            float bv0 = Bsrc[(k + tig) * CC + n + gid];
            float bv1 = Bsrc[(k + tig + 4) * CC + n + gid];
            unsigned b0 = isv ? f2tf(bv0) : __float_as_uint(bv0);
            unsigned b1 = isv ? f2tf(bv1) : __float_as_uint(bv1);
            mma_tf32(c0, c1, c2, c3, a0, a1, a2, a3, b0, b1);
        }
        int r0 = row0 + mrow + gid;
        if (!isv) {
            g_y[(size_t)r0 * CC + n + 2 * tig]           = f2tf_f(c0);
            g_y[(size_t)r0 * CC + n + 2 * tig + 1]       = f2tf_f(c1);
            g_y[(size_t)(r0 + 8) * CC + n + 2 * tig]     = f2tf_f(c2);
            g_y[(size_t)(r0 + 8) * CC + n + 2 * tig + 1] = f2tf_f(c3);
        } else {
            // permuted store: col h -> (h&7)*16 + (h>>3)
            int col0 = 32 * tig + nt8;
            g_v[(size_t)r0 * HSZ + col0]            = f2tf_f(c0);
            g_v[(size_t)r0 * HSZ + col0 + 16]       = f2tf_f(c1);
            g_v[(size_t)(r0 + 8) * HSZ + col0]      = f2tf_f(c2);
            g_v[(size_t)(r0 + 8) * HSZ + col0 + 16] = f2tf_f(c3);
        }
    }
}

// ---------------------------------------------------------------------------
// K2b: score[b,t,u] = (y[b,t,:] . x[b,u,:]) * C^-0.5
// One u-chunk per block (stateless) -> single barrier, low regs.
// grid(8, 8, 32) = (t_tile, u_chunk, b), block(128), dyn smem = 64*144*4
// ---------------------------------------------------------------------------
__global__ void __launch_bounds__(128) k_score(const float* __restrict__ x) {
    extern __shared__ float sxp[];  // [64][144] permuted tf32 x chunk
    int tid = threadIdx.x;
    int lane = tid & 31, w = tid >> 5, g = lane >> 2, t = lane & 3;
    int b = blockIdx.z;
    int t0 = blockIdx.x * 64;
    int u0 = blockIdx.y * 64;
    int mrow = w * 16;
    int R0 = t0 + mrow + g, R1 = R0 + 8;
    const float scl = 0.08838834764831843f;  // 128^-0.5

    // cooperative permuted load of x chunk (issue before A loads for overlap)
    for (int f = tid; f < 64 * CC / 4; f += 128) {
        int r = f >> 5, c4 = f & 31;
        float4 v4 = *reinterpret_cast<const float4*>(&x[(size_t)(b * TT + u0 + r) * CC + c4 * 4]);
        float* dst = &sxp[r * 144 + c4];  // element j goes to j*36 + c4
        dst[0]   = f2tf_f(v4.x);
        dst[36]  = f2tf_f(v4.y);
        dst[72]  = f2tf_f(v4.z);
        dst[108] = f2tf_f(v4.w);
    }

    // A fragments from g_y (already tf32)
    unsigned a0r[16], a1r[16], a2r[16], a3r[16];
    const float* y0 = g_y + (size_t)(b * TT + R0) * CC;
    const float* y1 = g_y + (size_t)(b * TT + R1) * CC;
#pragma unroll
    for (int kk = 0; kk < 16; kk++) {
        int c = 8 * kk + t;
        a0r[kk] = __float_as_uint(y0[c]);
        a1r[kk] = __float_as_uint(y1[c]);
        a2r[kk] = __float_as_uint(y0[c + 4]);
        a3r[kk] = __float_as_uint(y1[c + 4]);
    }
    __syncthreads();

#pragma unroll
    for (int nt = 0; nt < 8; nt++) {
        int brow = nt * 8 + g;
        const float4* bp = reinterpret_cast<const float4*>(&sxp[brow * 144 + t * 36]);
        float c0 = 0, c1 = 0, c2 = 0, c3 = 0;
#pragma unroll
        for (int j = 0; j < 8; j++) {
            float4 bq = bp[j];  // holds K pairs for kk=2j, 2j+1
            mma_tf32(c0, c1, c2, c3, a0r[2 * j], a1r[2 * j], a2r[2 * j], a3r[2 * j],
                     __float_as_uint(bq.x), __float_as_uint(bq.y));
            mma_tf32(c0, c1, c2, c3, a0r[2 * j + 1], a1r[2 * j + 1], a2r[2 * j + 1], a3r[2 * j + 1],
                     __float_as_uint(bq.z), __float_as_uint(bq.w));
        }
        float* d0 = g_score + ((size_t)b * TT + R0) * TT + u0 + nt * 8;
        float* d1 = g_score + ((size_t)b * TT + R1) * TT + u0 + nt * 8;
        *reinterpret_cast<float2*>(&d0[2 * t]) = make_float2(c0 * scl, c1 * scl);
        *reinterpret_cast<float2*>(&d1[2 * t]) = make_float2(c2 * scl, c3 * scl);
    }
}

// ---------------------------------------------------------------------------
// K3: softmax (no max subtraction; scores O(10), fp32 exp safe) + P@V, tf32 mma.
// block 128 = 4 warps; t-tile 64 rows; warp = 16 rows x FULL 128 cols
//   -> no exp duplication (each (row,u) exp'd exactly once per block).
// K-axis reindex: mma slice (sh,kk) covers u = sh*32 + 8j + 4i + kk; lane (g,t)
//   gathers score/adj for its rows at u = sh*32+8t+{0..7} = 2 contiguous float4.
// V smem rows permuted: chunk row u at rho = (u&32) + (u&7)*4 + ((u>>3)&3)
//   -> B-fragment rows for slice (sh,kk) are rho = sh*32+kk*4+t and +16,
//      consecutive in t => LDS.128 conflict-free (bank = t+4g mod 8, distinct).
// Permuted g_v columns: h -> (h&7)*16+(h>>3) => per row, the 16 B-fragment
//   floats for col-group g live at float4 indices [4g, 4g+4) => 4 LDS.128/row.
// cp.async double-buffered 64-row V chunks.
// grid(8, 8, 32) = (s, t_tile, b) -- s fastest for score L2 reuse.
// dyn smem = 2*64*33*16 = 67584
// ---------------------------------------------------------------------------
__global__ void __launch_bounds__(128, 3) k_attn(const float* __restrict__ adj,
                                                 float* __restrict__ out) {
    extern __shared__ float sv[];
    int tid = threadIdx.x, lane = tid & 31, w = tid >> 5;
    int g = lane >> 2, t = lane & 3;
    int s = blockIdx.x, b = blockIdx.z;
    int t0 = blockIdx.y * 64;
    int mrow = w * 16;
    int r0 = t0 + mrow + g, r1 = r0 + 8;

    const float* s0 = g_score + ((size_t)b * TT + r0) * TT;
    const float* s1 = g_score + ((size_t)b * TT + r1) * TT;
    const float* a0p = adj + (((size_t)b * SS + s) * TT + r0) * TT;
    const float* a1p = adj + (((size_t)b * SS + s) * TT + r1) * TT;
    const float4* gv4 = reinterpret_cast<const float4*>(g_v + (size_t)b * TT * HSZ);
    const float4* sv4 = reinterpret_cast<const float4*>(sv);
    unsigned svb = (unsigned)__cvta_generic_to_shared(sv);

    float acc[16][4];
#pragma unroll
    for (int e = 0; e < 16; e++) {
        acc[e][0] = 0.f; acc[e][1] = 0.f; acc[e][2] = 0.f; acc[e][3] = 0.f;
    }
    float l0 = 0.f, l1 = 0.f;

    // prologue: chunk 0 -> buffer 0 (permuted row placement)
    for (int f = tid; f < 2048; f += 128) {
        int u = f >> 5, c16 = f & 31;
        int rho = (u & 32) + ((u & 7) << 2) + ((u >> 3) & 3);
        cp_async16(svb + (unsigned)((rho * 33 + c16) << 4), gv4 + (size_t)u * 32 + c16);
    }
    asm volatile("cp.async.commit_group;" ::: "memory");

    for (int ch = 0; ch < 8; ch++) {
        int u0 = ch * 64;
        if (ch < 7) {
            unsigned boff = (unsigned)(((ch + 1) & 1) * 33792);
            int ubase = u0 + 64;
            for (int f = tid; f < 2048; f += 128) {
                int u = f >> 5, c16 = f & 31;
                int rho = (u & 32) + ((u & 7) << 2) + ((u >> 3) & 3);
                cp_async16(svb + boff + (unsigned)((rho * 33 + c16) << 4),
                           gv4 + (size_t)(ubase + u) * 32 + c16);
            }
            asm volatile("cp.async.commit_group;" ::: "memory");
            asm volatile("cp.async.wait_group 1;" ::: "memory");
        } else {
            asm volatile("cp.async.wait_group 0;" ::: "memory");
        }
        __syncthreads();
        const float4* vb = sv4 + (ch & 1) * 2112;

#pragma unroll
        for (int sh = 0; sh < 2; sh++) {
            int cb = u0 + sh * 32 + 8 * t;
            float w0[8], w1[8];
            {
                float4 xa = *reinterpret_cast<const float4*>(s0 + cb);
                float4 xb = *reinterpret_cast<const float4*>(s0 + cb + 4);
                float4 ya = *reinterpret_cast<const float4*>(a0p + cb);
                float4 yb = *reinterpret_cast<const float4*>(a0p + cb + 4);
                w0[0] = __expf(xa.x * ya.x); w0[1] = __expf(xa.y * ya.y);
                w0[2] = __expf(xa.z * ya.z); w0[3] = __expf(xa.w * ya.w);
                w0[4] = __expf(xb.x * yb.x); w0[5] = __expf(xb.y * yb.y);
                w0[6] = __expf(xb.z * yb.z); w0[7] = __expf(xb.w * yb.w);
                l0 += ((w0[0] + w0[1]) + (w0[2] + w0[3])) + ((w0[4] + w0[5]) + (w0[6] + w0[7]));
            }
            {
                float4 xa = *reinterpret_cast<const float4*>(s1 + cb);
                float4 xb = *reinterpret_cast<const float4*>(s1 + cb + 4);
                float4 ya = *reinterpret_cast<const float4*>(a1p + cb);
                float4 yb = *reinterpret_cast<const float4*>(a1p + cb + 4);
                w1[0] = __expf(xa.x * ya.x); w1[1] = __expf(xa.y * ya.y);
                w1[2] = __expf(xa.z * ya.z); w1[3] = __expf(xa.w * ya.w);
                w1[4] = __expf(xb.x * yb.x); w1[5] = __expf(xb.y * yb.y);
                w1[6] = __expf(xb.z * yb.z); w1[7] = __expf(xb.w * yb.w);
                l1 += ((w1[0] + w1[1]) + (w1[2] + w1[3])) + ((w1[4] + w1[5]) + (w1[6] + w1[7]));
            }
#pragma unroll
            for (int kk = 0; kk < 4; kk++) {
                int rlo = sh * 32 + kk * 4 + t;
                const float4* plo = vb + rlo * 33 + 4 * g;
                const float4* phi = plo + 16 * 33;
                unsigned p0 = f2tf(w0[kk]);
                unsigned p1 = f2tf(w1[kk]);
                unsigned p2 = f2tf(w0[4 + kk]);
                unsigned p3 = f2tf(w1[4 + kk]);
#pragma unroll
                for (int j = 0; j < 4; j++) {
                    float4 bl = plo[j];
                    float4 bh = phi[j];
                    int e = 4 * j;
                    mma_tf32(acc[e][0], acc[e][1], acc[e][2], acc[e][3], p0, p1, p2, p3,
                             __float_as_uint(bl.x), __float_as_uint(bh.x));
                    mma_tf32(acc[e + 1][0], acc[e + 1][1], acc[e + 1][2], acc[e + 1][3],
                             p0, p1, p2, p3, __float_as_uint(bl.y), __float_as_uint(bh.y));
                    mma_tf32(acc[e + 2][0], acc[e + 2][1], acc[e + 2][2], acc[e + 2][3],
                             p0, p1, p2, p3, __float_as_uint(bl.z), __float_as_uint(bh.z));
                    mma_tf32(acc[e + 3][0], acc[e + 3][1], acc[e + 3][2], acc[e + 3][3],
                             p0, p1, p2, p3, __float_as_uint(bl.w), __float_as_uint(bh.w));
                }
            }
        }
        __syncthreads();
    }

    // epilogue: quad-reduce row sums over t lanes, normalize, store
    l0 += __shfl_xor_sync(0xffffffffu, l0, 1);
    l0 += __shfl_xor_sync(0xffffffffu, l0, 2);
    l1 += __shfl_xor_sync(0xffffffffu, l1, 1);
    l1 += __shfl_xor_sync(0xffffffffu, l1, 2);
    float rl0 = 1.f / l0, rl1 = 1.f / l1;

    float* ob0 = out + (((size_t)b * SS + s) * TT + r0) * HSZ;
    float* ob1 = out + (((size_t)b * SS + s) * TT + r1) * HSZ;
#pragma unroll
    for (int e = 0; e < 16; e++) {
        int c = 8 * e + 2 * t;
        *reinterpret_cast<float2*>(&ob0[c]) = make_float2(acc[e][0] * rl0, acc[e][1] * rl0);
        *reinterpret_cast<float2*>(&ob1[c]) = make_float2(acc[e][2] * rl1, acc[e][3] * rl1);
    }
}

// ---------------------------------------------------------------------------
extern "C" void kernel_launch(void* const* d_in, const int* in_sizes, int n_in,
                              void* d_out, int out_size) {
    const float* x   = (const float*)d_in[0];
    const float* adj = (const float*)d_in[1];
    const float* Wq  = (const float*)d_in[2];
    const float* Wk  = (const float*)d_in[3];
    const float* Wv  = (const float*)d_in[4];
    float* out = (float*)d_out;

    const int smem_k1 = 128 * 132 * 4;     // 67584
    const int smem_k2a = 64 * 132 * 4;     // 33792
    const int smem_k2b = 64 * 144 * 4;     // 36864
    const int smem_k3 = 2 * 64 * 33 * 16;  // 67584 (double-buffered permuted V)

    cudaFuncSetAttribute(k_wqwk, cudaFuncAttributeMaxDynamicSharedMemorySize, smem_k1);
    cudaFuncSetAttribute(k_yv, cudaFuncAttributeMaxDynamicSharedMemorySize, smem_k2a);
    cudaFuncSetAttribute(k_score, cudaFuncAttributeMaxDynamicSharedMemorySize, smem_k2b);
    cudaFuncSetAttribute(k_attn, cudaFuncAttributeMaxDynamicSharedMemorySize, smem_k3);

    k_wqwk<<<128, 128, smem_k1>>>(Wq, Wk);
    k_yv<<<(BB * TT) / 64, 128, smem_k2a>>>(x, Wv);
    k_score<<<dim3(TT / 64, TT / 64, BB), 128, smem_k2b>>>(x);
    k_attn<<<dim3(SS, TT / 64, BB), 128, smem_k3>>>(adj, out);
}

// round 10
// speedup vs baseline: 1.6890x; 1.0047x over previous
#include <cuda_runtime.h>
#include <cstdint>
#include <cstddef>

// Problem constants
#define BB 32
#define SS 8
#define TT 512
#define CC 128
#define HSZ 128

// Scratch (device globals; no runtime allocation allowed)
__device__ float g_M[CC * CC];                       // Wq @ Wk^T, tf32-rounded
__device__ float g_y[BB * TT * CC];                  // x @ M, tf32-rounded
__device__ float g_v[BB * TT * HSZ];                 // x @ Wv, tf32, COLUMN-PERMUTED: h -> (h&7)*16 + (h>>3)
__device__ float g_score[(size_t)BB * TT * TT];      // fp32 scores (33.5 MB)

__device__ __forceinline__ unsigned f2tf(float x) {
    unsigned u;
    asm("cvt.rna.tf32.f32 %0, %1;" : "=r"(u) : "f"(x));
    return u;
}
__device__ __forceinline__ float f2tf_f(float x) { return __uint_as_float(f2tf(x)); }

__device__ __forceinline__ void mma_tf32(float& c0, float& c1, float& c2, float& c3,
                                         unsigned a0, unsigned a1, unsigned a2, unsigned a3,
                                         unsigned b0, unsigned b1) {
    asm volatile(
        "mma.sync.aligned.m16n8k8.row.col.f32.tf32.tf32.f32 "
        "{%0,%1,%2,%3},{%4,%5,%6,%7},{%8,%9},{%0,%1,%2,%3};\n"
        : "+f"(c0), "+f"(c1), "+f"(c2), "+f"(c3)
        : "r"(a0), "r"(a1), "r"(a2), "r"(a3), "r"(b0), "r"(b1));
}

__device__ __forceinline__ void cp_async16(unsigned dst, const void* src) {
    asm volatile("cp.async.cg.shared.global [%0], [%1], 16;" :: "r"(dst), "l"(src) : "memory");
}

// ---------------------------------------------------------------------------
// K1: M = Wq @ Wk^T  (fp32 FFMA, rounded to tf32 on store)
// ---------------------------------------------------------------------------
__global__ void k_wqwk(const float* __restrict__ Wq, const float* __restrict__ Wk) {
    extern __shared__ float sm[];  // sWk[128][132]
    int tid = threadIdx.x;
    int c1 = blockIdx.x;
    for (int i = tid; i < CC * CC; i += 128) {
        sm[(i >> 7) * 132 + (i & 127)] = Wk[i];
    }
    __syncthreads();
    const float* wqr = Wq + c1 * CC;
    float acc = 0.f;
#pragma unroll 8
    for (int h = 0; h < CC; h++) acc += wqr[h] * sm[tid * 132 + h];
    g_M[c1 * CC + tid] = f2tf_f(acc);
}

// ---------------------------------------------------------------------------
// K2a: y = x @ M,  v = x @ Wv   (tf32 mma). v stored column-permuted.
// grid(B*T/64), block(128), dyn smem = 64*132*4
// ---------------------------------------------------------------------------
__global__ void __launch_bounds__(128) k_yv(const float* __restrict__ x,
                                            const float* __restrict__ Wv) {
    extern __shared__ float sm[];  // sx[64][132] tf32-rounded
    int tid = threadIdx.x;
    int row0 = blockIdx.x * 64;
    for (int f = tid; f < 64 * CC / 4; f += 128) {
        int r = f >> 5, c = (f & 31) * 4;
        float4 v4 = *reinterpret_cast<const float4*>(&x[(size_t)(row0 + r) * CC + c]);
        float4 o;
        o.x = f2tf_f(v4.x); o.y = f2tf_f(v4.y); o.z = f2tf_f(v4.z); o.w = f2tf_f(v4.w);
        *reinterpret_cast<float4*>(&sm[r * 132 + c]) = o;
    }
    __syncthreads();
    int lane = tid & 31, w = tid >> 5;
    int gid = lane >> 2, tig = lane & 3;
    int mrow = w * 16;
    for (int nt = 0; nt < 32; nt++) {
        bool isv = nt >= 16;
        const float* Bsrc = isv ? Wv : g_M;
        int nt8 = nt & 15;
        int n = nt8 * 8;
        float c0 = 0, c1 = 0, c2 = 0, c3 = 0;
#pragma unroll
        for (int kk = 0; kk < 16; kk++) {
            int k = kk * 8;
            unsigned a0 = __float_as_uint(sm[(mrow + gid) * 132 + k + tig]);
            unsigned a1 = __float_as_uint(sm[(mrow + gid + 8) * 132 + k + tig]);
            unsigned a2 = __float_as_uint(sm[(mrow + gid) * 132 + k + tig + 4]);
            unsigned a3 = __float_as_uint(sm[(mrow + gid + 8) * 132 + k + tig + 4]);
            float bv0 = Bsrc[(k + tig) * CC + n + gid];
            float bv1 = Bsrc[(k + tig + 4) * CC + n + gid];
            unsigned b0 = isv ? f2tf(bv0) : __float_as_uint(bv0);
            unsigned b1 = isv ? f2tf(bv1) : __float_as_uint(bv1);
            mma_tf32(c0, c1, c2, c3, a0, a1, a2, a3, b0, b1);
        }
        int r0 = row0 + mrow + gid;
        if (!isv) {
            g_y[(size_t)r0 * CC + n + 2 * tig]           = f2tf_f(c0);
            g_y[(size_t)r0 * CC + n + 2 * tig + 1]       = f2tf_f(c1);
            g_y[(size_t)(r0 + 8) * CC + n + 2 * tig]     = f2tf_f(c2);
            g_y[(size_t)(r0 + 8) * CC + n + 2 * tig + 1] = f2tf_f(c3);
        } else {
            // permuted store: col h -> (h&7)*16 + (h>>3)
            int col0 = 32 * tig + nt8;
            g_v[(size_t)r0 * HSZ + col0]            = f2tf_f(c0);
            g_v[(size_t)r0 * HSZ + col0 + 16]       = f2tf_f(c1);
            g_v[(size_t)(r0 + 8) * HSZ + col0]      = f2tf_f(c2);
            g_v[(size_t)(r0 + 8) * HSZ + col0 + 16] = f2tf_f(c3);
        }
    }
}

// ---------------------------------------------------------------------------
// K2b: score[b,t,u] = (y[b,t,:] . x[b,u,:]) * C^-0.5
// One u-chunk per block (stateless) -> single barrier, low regs.
// grid(8, 8, 32) = (t_tile, u_chunk, b), block(128), dyn smem = 64*144*4
// ---------------------------------------------------------------------------
__global__ void __launch_bounds__(128) k_score(const float* __restrict__ x) {
    extern __shared__ float sxp[];  // [64][144] permuted tf32 x chunk
    int tid = threadIdx.x;
    int lane = tid & 31, w = tid >> 5, g = lane >> 2, t = lane & 3;
    int b = blockIdx.z;
    int t0 = blockIdx.x * 64;
    int u0 = blockIdx.y * 64;
    int mrow = w * 16;
    int R0 = t0 + mrow + g, R1 = R0 + 8;
    const float scl = 0.08838834764831843f;  // 128^-0.5

    // cooperative permuted load of x chunk (issue before A loads for overlap)
    for (int f = tid; f < 64 * CC / 4; f += 128) {
        int r = f >> 5, c4 = f & 31;
        float4 v4 = *reinterpret_cast<const float4*>(&x[(size_t)(b * TT + u0 + r) * CC + c4 * 4]);
        float* dst = &sxp[r * 144 + c4];  // element j goes to j*36 + c4
        dst[0]   = f2tf_f(v4.x);
        dst[36]  = f2tf_f(v4.y);
        dst[72]  = f2tf_f(v4.z);
        dst[108] = f2tf_f(v4.w);
    }

    // A fragments from g_y (already tf32)
    unsigned a0r[16], a1r[16], a2r[16], a3r[16];
    const float* y0 = g_y + (size_t)(b * TT + R0) * CC;
    const float* y1 = g_y + (size_t)(b * TT + R1) * CC;
#pragma unroll
    for (int kk = 0; kk < 16; kk++) {
        int c = 8 * kk + t;
        a0r[kk] = __float_as_uint(y0[c]);
        a1r[kk] = __float_as_uint(y1[c]);
        a2r[kk] = __float_as_uint(y0[c + 4]);
        a3r[kk] = __float_as_uint(y1[c + 4]);
    }
    __syncthreads();

#pragma unroll
    for (int nt = 0; nt < 8; nt++) {
        int brow = nt * 8 + g;
        const float4* bp = reinterpret_cast<const float4*>(&sxp[brow * 144 + t * 36]);
        float c0 = 0, c1 = 0, c2 = 0, c3 = 0;
#pragma unroll
        for (int j = 0; j < 8; j++) {
            float4 bq = bp[j];  // holds K pairs for kk=2j, 2j+1
            mma_tf32(c0, c1, c2, c3, a0r[2 * j], a1r[2 * j], a2r[2 * j], a3r[2 * j],
                     __float_as_uint(bq.x), __float_as_uint(bq.y));
            mma_tf32(c0, c1, c2, c3, a0r[2 * j + 1], a1r[2 * j + 1], a2r[2 * j + 1], a3r[2 * j + 1],
                     __float_as_uint(bq.z), __float_as_uint(bq.w));
        }
        float* d0 = g_score + ((size_t)b * TT + R0) * TT + u0 + nt * 8;
        float* d1 = g_score + ((size_t)b * TT + R1) * TT + u0 + nt * 8;
        *reinterpret_cast<float2*>(&d0[2 * t]) = make_float2(c0 * scl, c1 * scl);
        *reinterpret_cast<float2*>(&d1[2 * t]) = make_float2(c2 * scl, c3 * scl);
    }
}

// ---------------------------------------------------------------------------
// K3: softmax (no max subtraction; scores O(10), fp32 exp safe) + P@V, tf32 mma.
// block 128 = 4 warps; t-tile 64 rows; warp = 16 rows x FULL 128 cols
//   -> no exp duplication (each (row,u) exp'd exactly once per block).
// K-axis reindex: mma slice (sh,kk) covers u = sh*32 + 8j + 4i + kk; lane (g,t)
//   gathers score/adj for its rows at u = sh*32+8t+{0..7} = 2 contiguous float4.
// V smem rows permuted: chunk row u at rho = (u&32) + (u&7)*4 + ((u>>3)&3)
//   -> B-fragment rows for slice (sh,kk) are rho = sh*32+kk*4+t and +16,
//      consecutive in t => LDS.128 conflict-free (bank = t+4g mod 8, distinct).
// Permuted g_v columns: h -> (h&7)*16+(h>>3) => per row, the 16 B-fragment
//   floats for col-group g live at float4 indices [4g, 4g+4) => 4 LDS.128/row.
// cp.async double-buffered 64-row V chunks.
// grid(8, 8, 32) = (s, t_tile, b) -- s fastest for score L2 reuse.
// dyn smem = 2*64*33*16 = 67584
// ---------------------------------------------------------------------------
__global__ void __launch_bounds__(128, 3) k_attn(const float* __restrict__ adj,
                                                 float* __restrict__ out) {
    extern __shared__ float sv[];
    int tid = threadIdx.x, lane = tid & 31, w = tid >> 5;
    int g = lane >> 2, t = lane & 3;
    int s = blockIdx.x, b = blockIdx.z;
    int t0 = blockIdx.y * 64;
    int mrow = w * 16;
    int r0 = t0 + mrow + g, r1 = r0 + 8;

    const float* s0 = g_score + ((size_t)b * TT + r0) * TT;
    const float* s1 = g_score + ((size_t)b * TT + r1) * TT;
    const float* a0p = adj + (((size_t)b * SS + s) * TT + r0) * TT;
    const float* a1p = adj + (((size_t)b * SS + s) * TT + r1) * TT;
    const float4* gv4 = reinterpret_cast<const float4*>(g_v + (size_t)b * TT * HSZ);
    const float4* sv4 = reinterpret_cast<const float4*>(sv);
    unsigned svb = (unsigned)__cvta_generic_to_shared(sv);

    float acc[16][4];
#pragma unroll
    for (int e = 0; e < 16; e++) {
        acc[e][0] = 0.f; acc[e][1] = 0.f; acc[e][2] = 0.f; acc[e][3] = 0.f;
    }
    float l0 = 0.f, l1 = 0.f;

    // prologue: chunk 0 -> buffer 0 (permuted row placement)
    for (int f = tid; f < 2048; f += 128) {
        int u = f >> 5, c16 = f & 31;
        int rho = (u & 32) + ((u & 7) << 2) + ((u >> 3) & 3);
        cp_async16(svb + (unsigned)((rho * 33 + c16) << 4), gv4 + (size_t)u * 32 + c16);
    }
    asm volatile("cp.async.commit_group;" ::: "memory");

    for (int ch = 0; ch < 8; ch++) {
        int u0 = ch * 64;
        if (ch < 7) {
            unsigned boff = (unsigned)(((ch + 1) & 1) * 33792);
            int ubase = u0 + 64;
            for (int f = tid; f < 2048; f += 128) {
                int u = f >> 5, c16 = f & 31;
                int rho = (u & 32) + ((u & 7) << 2) + ((u >> 3) & 3);
                cp_async16(svb + boff + (unsigned)((rho * 33 + c16) << 4),
                           gv4 + (size_t)(ubase + u) * 32 + c16);
            }
            asm volatile("cp.async.commit_group;" ::: "memory");
            asm volatile("cp.async.wait_group 1;" ::: "memory");
        } else {
            asm volatile("cp.async.wait_group 0;" ::: "memory");
        }
        __syncthreads();
        const float4* vb = sv4 + (ch & 1) * 2112;

#pragma unroll
        for (int sh = 0; sh < 2; sh++) {
            int cb = u0 + sh * 32 + 8 * t;
            float w0[8], w1[8];
            {
                float4 xa = *reinterpret_cast<const float4*>(s0 + cb);
                float4 xb = *reinterpret_cast<const float4*>(s0 + cb + 4);
                float4 ya = *reinterpret_cast<const float4*>(a0p + cb);
                float4 yb = *reinterpret_cast<const float4*>(a0p + cb + 4);
                w0[0] = __expf(xa.x * ya.x); w0[1] = __expf(xa.y * ya.y);
                w0[2] = __expf(xa.z * ya.z); w0[3] = __expf(xa.w * ya.w);
                w0[4] = __expf(xb.x * yb.x); w0[5] = __expf(xb.y * yb.y);
                w0[6] = __expf(xb.z * yb.z); w0[7] = __expf(xb.w * yb.w);
                l0 += ((w0[0] + w0[1]) + (w0[2] + w0[3])) + ((w0[4] + w0[5]) + (w0[6] + w0[7]));
            }
            {
                float4 xa = *reinterpret_cast<const float4*>(s1 + cb);
                float4 xb = *reinterpret_cast<const float4*>(s1 + cb + 4);
                float4 ya = *reinterpret_cast<const float4*>(a1p + cb);
                float4 yb = *reinterpret_cast<const float4*>(a1p + cb + 4);
                w1[0] = __expf(xa.x * ya.x); w1[1] = __expf(xa.y * ya.y);
                w1[2] = __expf(xa.z * ya.z); w1[3] = __expf(xa.w * ya.w);
                w1[4] = __expf(xb.x * yb.x); w1[5] = __expf(xb.y * yb.y);
                w1[6] = __expf(xb.z * yb.z); w1[7] = __expf(xb.w * yb.w);
                l1 += ((w1[0] + w1[1]) + (w1[2] + w1[3])) + ((w1[4] + w1[5]) + (w1[6] + w1[7]));
            }
#pragma unroll
            for (int kk = 0; kk < 4; kk++) {
                int rlo = sh * 32 + kk * 4 + t;
                const float4* plo = vb + rlo * 33 + 4 * g;
                const float4* phi = plo + 16 * 33;
                unsigned p0 = f2tf(w0[kk]);
                unsigned p1 = f2tf(w1[kk]);
                unsigned p2 = f2tf(w0[4 + kk]);
                unsigned p3 = f2tf(w1[4 + kk]);
#pragma unroll
                for (int j = 0; j < 4; j++) {
                    float4 bl = plo[j];
                    float4 bh = phi[j];
                    int e = 4 * j;
                    mma_tf32(acc[e][0], acc[e][1], acc[e][2], acc[e][3], p0, p1, p2, p3,
                             __float_as_uint(bl.x), __float_as_uint(bh.x));
                    mma_tf32(acc[e + 1][0], acc[e + 1][1], acc[e + 1][2], acc[e + 1][3],
                             p0, p1, p2, p3, __float_as_uint(bl.y), __float_as_uint(bh.y));
                    mma_tf32(acc[e + 2][0], acc[e + 2][1], acc[e + 2][2], acc[e + 2][3],
                             p0, p1, p2, p3, __float_as_uint(bl.z), __float_as_uint(bh.z));
                    mma_tf32(acc[e + 3][0], acc[e + 3][1], acc[e + 3][2], acc[e + 3][3],
                             p0, p1, p2, p3, __float_as_uint(bl.w), __float_as_uint(bh.w));
                }
            }
        }
        __syncthreads();
    }

    // epilogue: quad-reduce row sums over t lanes, normalize, store
    l0 += __shfl_xor_sync(0xffffffffu, l0, 1);
    l0 += __shfl_xor_sync(0xffffffffu, l0, 2);
    l1 += __shfl_xor_sync(0xffffffffu, l1, 1);
    l1 += __shfl_xor_sync(0xffffffffu, l1, 2);
    float rl0 = 1.f / l0, rl1 = 1.f / l1;

    float* ob0 = out + (((size_t)b * SS + s) * TT + r0) * HSZ;
    float* ob1 = out + (((size_t)b * SS + s) * TT + r1) * HSZ;
#pragma unroll
    for (int e = 0; e < 16; e++) {
        int c = 8 * e + 2 * t;
        *reinterpret_cast<float2*>(&ob0[c]) = make_float2(acc[e][0] * rl0, acc[e][1] * rl0);
        *reinterpret_cast<float2*>(&ob1[c]) = make_float2(acc[e][2] * rl1, acc[e][3] * rl1);
    }
}

// ---------------------------------------------------------------------------
extern "C" void kernel_launch(void* const* d_in, const int* in_sizes, int n_in,
                              void* d_out, int out_size) {
    const float* x   = (const float*)d_in[0];
    const float* adj = (const float*)d_in[1];
    const float* Wq  = (const float*)d_in[2];
    const float* Wk  = (const float*)d_in[3];
    const float* Wv  = (const float*)d_in[4];
    float* out = (float*)d_out;

    const int smem_k1 = 128 * 132 * 4;     // 67584
    const int smem_k2a = 64 * 132 * 4;     // 33792
    const int smem_k2b = 64 * 144 * 4;     // 36864
    const int smem_k3 = 2 * 64 * 33 * 16;  // 67584 (double-buffered permuted V)

    cudaFuncSetAttribute(k_wqwk, cudaFuncAttributeMaxDynamicSharedMemorySize, smem_k1);
    cudaFuncSetAttribute(k_yv, cudaFuncAttributeMaxDynamicSharedMemorySize, smem_k2a);
    cudaFuncSetAttribute(k_score, cudaFuncAttributeMaxDynamicSharedMemorySize, smem_k2b);
    cudaFuncSetAttribute(k_attn, cudaFuncAttributeMaxDynamicSharedMemorySize, smem_k3);

    k_wqwk<<<128, 128, smem_k1>>>(Wq, Wk);
    k_yv<<<(BB * TT) / 64, 128, smem_k2a>>>(x, Wv);
    k_score<<<dim3(TT / 64, TT / 64, BB), 128, smem_k2b>>>(x);
    k_attn<<<dim3(SS, TT / 64, BB), 128, smem_k3>>>(adj, out);
}

// round 16
// speedup vs baseline: 1.8198x; 1.0774x over previous
#include <cuda_runtime.h>
#include <cstdint>
#include <cstddef>

// Problem constants
#define BB 32
#define SS 8
#define TT 512
#define CC 128
#define HSZ 128

// Scratch (device globals; no runtime allocation allowed)
__device__ float g_M[CC * CC];                       // Wq @ Wk^T, tf32-rounded
__device__ float g_y[BB * TT * CC];                  // x @ M, tf32-rounded
__device__ float g_v[BB * TT * HSZ];                 // x @ Wv, tf32, COLUMN-PERMUTED: h -> (h&7)*16 + (h>>3)
__device__ float g_score[(size_t)BB * TT * TT];      // fp32 scores (33.5 MB)

__device__ __forceinline__ unsigned f2tf(float x) {
    unsigned u;
    asm("cvt.rna.tf32.f32 %0, %1;" : "=r"(u) : "f"(x));
    return u;
}
__device__ __forceinline__ float f2tf_f(float x) { return __uint_as_float(f2tf(x)); }

__device__ __forceinline__ void mma_tf32(float& c0, float& c1, float& c2, float& c3,
                                         unsigned a0, unsigned a1, unsigned a2, unsigned a3,
                                         unsigned b0, unsigned b1) {
    asm volatile(
        "mma.sync.aligned.m16n8k8.row.col.f32.tf32.tf32.f32 "
        "{%0,%1,%2,%3},{%4,%5,%6,%7},{%8,%9},{%0,%1,%2,%3};\n"
        : "+f"(c0), "+f"(c1), "+f"(c2), "+f"(c3)
        : "r"(a0), "r"(a1), "r"(a2), "r"(a3), "r"(b0), "r"(b1));
}

__device__ __forceinline__ void cp_async16(unsigned dst, const void* src) {
    asm volatile("cp.async.cg.shared.global [%0], [%1], 16;" :: "r"(dst), "l"(src) : "memory");
}

// ---------------------------------------------------------------------------
// K1: M = Wq @ Wk^T  (fp32 FFMA, rounded to tf32 on store)
// ---------------------------------------------------------------------------
__global__ void k_wqwk(const float* __restrict__ Wq, const float* __restrict__ Wk) {
    extern __shared__ float sm[];  // sWk[128][132]
    int tid = threadIdx.x;
    int c1 = blockIdx.x;
    for (int i = tid; i < CC * CC; i += 128) {
        sm[(i >> 7) * 132 + (i & 127)] = Wk[i];
    }
    __syncthreads();
    const float* wqr = Wq + c1 * CC;
    float acc = 0.f;
#pragma unroll 8
    for (int h = 0; h < CC; h++) acc += wqr[h] * sm[tid * 132 + h];
    g_M[c1 * CC + tid] = f2tf_f(acc);
}

// ---------------------------------------------------------------------------
// K2a: y = x @ M,  v = x @ Wv   (tf32 mma). v stored column-permuted.
// grid(B*T/64), block(128), dyn smem = 64*132*4
// ---------------------------------------------------------------------------
__global__ void __launch_bounds__(128) k_yv(const float* __restrict__ x,
                                            const float* __restrict__ Wv) {
    extern __shared__ float sm[];  // sx[64][132] tf32-rounded
    int tid = threadIdx.x;
    int row0 = blockIdx.x * 64;
    for (int f = tid; f < 64 * CC / 4; f += 128) {
        int r = f >> 5, c = (f & 31) * 4;
        float4 v4 = *reinterpret_cast<const float4*>(&x[(size_t)(row0 + r) * CC + c]);
        float4 o;
        o.x = f2tf_f(v4.x); o.y = f2tf_f(v4.y); o.z = f2tf_f(v4.z); o.w = f2tf_f(v4.w);
        *reinterpret_cast<float4*>(&sm[r * 132 + c]) = o;
    }
    __syncthreads();
    int lane = tid & 31, w = tid >> 5;
    int gid = lane >> 2, tig = lane & 3;
    int mrow = w * 16;
    for (int nt = 0; nt < 32; nt++) {
        bool isv = nt >= 16;
        const float* Bsrc = isv ? Wv : g_M;
        int nt8 = nt & 15;
        int n = nt8 * 8;
        float c0 = 0, c1 = 0, c2 = 0, c3 = 0;
#pragma unroll
        for (int kk = 0; kk < 16; kk++) {
            int k = kk * 8;
            unsigned a0 = __float_as_uint(sm[(mrow + gid) * 132 + k + tig]);
            unsigned a1 = __float_as_uint(sm[(mrow + gid + 8) * 132 + k + tig]);
            unsigned a2 = __float_as_uint(sm[(mrow + gid) * 132 + k + tig + 4]);
            unsigned a3 = __float_as_uint(sm[(mrow + gid + 8) * 132 + k + tig + 4]);
            float bv0 = Bsrc[(k + tig) * CC + n + gid];
            float bv1 = Bsrc[(k + tig + 4) * CC + n + gid];
            unsigned b0 = isv ? f2tf(bv0) : __float_as_uint(bv0);
            unsigned b1 = isv ? f2tf(bv1) : __float_as_uint(bv1);
            mma_tf32(c0, c1, c2, c3, a0, a1, a2, a3, b0, b1);
        }
        int r0 = row0 + mrow + gid;
        if (!isv) {
            g_y[(size_t)r0 * CC + n + 2 * tig]           = f2tf_f(c0);
            g_y[(size_t)r0 * CC + n + 2 * tig + 1]       = f2tf_f(c1);
            g_y[(size_t)(r0 + 8) * CC + n + 2 * tig]     = f2tf_f(c2);
            g_y[(size_t)(r0 + 8) * CC + n + 2 * tig + 1] = f2tf_f(c3);
        } else {
            // permuted store: col h -> (h&7)*16 + (h>>3)
            int col0 = 32 * tig + nt8;
            g_v[(size_t)r0 * HSZ + col0]            = f2tf_f(c0);
            g_v[(size_t)r0 * HSZ + col0 + 16]       = f2tf_f(c1);
            g_v[(size_t)(r0 + 8) * HSZ + col0]      = f2tf_f(c2);
            g_v[(size_t)(r0 + 8) * HSZ + col0 + 16] = f2tf_f(c3);
        }
    }
}

// ---------------------------------------------------------------------------
// K2b: score[b,t,u] = (y[b,t,:] . x[b,u,:]) * C^-0.5
// One u-chunk per block (stateless) -> single barrier, low regs.
// grid(8, 8, 32) = (t_tile, u_chunk, b), block(128), dyn smem = 64*144*4
// ---------------------------------------------------------------------------
__global__ void __launch_bounds__(128) k_score(const float* __restrict__ x) {
    extern __shared__ float sxp[];  // [64][144] permuted tf32 x chunk
    int tid = threadIdx.x;
    int lane = tid & 31, w = tid >> 5, g = lane >> 2, t = lane & 3;
    int b = blockIdx.z;
    int t0 = blockIdx.x * 64;
    int u0 = blockIdx.y * 64;
    int mrow = w * 16;
    int R0 = t0 + mrow + g, R1 = R0 + 8;
    const float scl = 0.08838834764831843f;  // 128^-0.5

    // cooperative permuted load of x chunk (issue before A loads for overlap)
    for (int f = tid; f < 64 * CC / 4; f += 128) {
        int r = f >> 5, c4 = f & 31;
        float4 v4 = *reinterpret_cast<const float4*>(&x[(size_t)(b * TT + u0 + r) * CC + c4 * 4]);
        float* dst = &sxp[r * 144 + c4];  // element j goes to j*36 + c4
        dst[0]   = f2tf_f(v4.x);
        dst[36]  = f2tf_f(v4.y);
        dst[72]  = f2tf_f(v4.z);
        dst[108] = f2tf_f(v4.w);
    }

    // A fragments from g_y (already tf32)
    unsigned a0r[16], a1r[16], a2r[16], a3r[16];
    const float* y0 = g_y + (size_t)(b * TT + R0) * CC;
    const float* y1 = g_y + (size_t)(b * TT + R1) * CC;
#pragma unroll
    for (int kk = 0; kk < 16; kk++) {
        int c = 8 * kk + t;
        a0r[kk] = __float_as_uint(y0[c]);
        a1r[kk] = __float_as_uint(y1[c]);
        a2r[kk] = __float_as_uint(y0[c + 4]);
        a3r[kk] = __float_as_uint(y1[c + 4]);
    }
    __syncthreads();

#pragma unroll
    for (int nt = 0; nt < 8; nt++) {
        int brow = nt * 8 + g;
        const float4* bp = reinterpret_cast<const float4*>(&sxp[brow * 144 + t * 36]);
        float c0 = 0, c1 = 0, c2 = 0, c3 = 0;
#pragma unroll
        for (int j = 0; j < 8; j++) {
            float4 bq = bp[j];  // holds K pairs for kk=2j, 2j+1
            mma_tf32(c0, c1, c2, c3, a0r[2 * j], a1r[2 * j], a2r[2 * j], a3r[2 * j],
                     __float_as_uint(bq.x), __float_as_uint(bq.y));
            mma_tf32(c0, c1, c2, c3, a0r[2 * j + 1], a1r[2 * j + 1], a2r[2 * j + 1], a3r[2 * j + 1],
                     __float_as_uint(bq.z), __float_as_uint(bq.w));
        }
        float* d0 = g_score + ((size_t)b * TT + R0) * TT + u0 + nt * 8;
        float* d1 = g_score + ((size_t)b * TT + R1) * TT + u0 + nt * 8;
        *reinterpret_cast<float2*>(&d0[2 * t]) = make_float2(c0 * scl, c1 * scl);
        *reinterpret_cast<float2*>(&d1[2 * t]) = make_float2(c2 * scl, c3 * scl);
    }
}

// ---------------------------------------------------------------------------
// K3: softmax (no max subtraction; scores O(10), fp32 exp safe) + P@V, tf32 mma.
// R9 structure + REGISTER-PIPELINED score/adj gathers: each 32-u sub-chunk's
// 8 LDG.128 are issued one sub-chunk ahead, so exp never waits on DRAM/L2.
// block 128 = 4 warps; t-tile 64 rows; warp = 16 rows x FULL 128 cols.
// V smem rows permuted (rho), columns permuted in g_v => conflict-free LDS.128.
// cp.async double-buffered 64-row V chunks.
// grid(8, 8, 32) = (s, t_tile, b); dyn smem = 2*64*33*16 = 67584
// ---------------------------------------------------------------------------
__global__ void __launch_bounds__(128, 3) k_attn(const float* __restrict__ adj,
                                                 float* __restrict__ out) {
    extern __shared__ float sv[];
    int tid = threadIdx.x, lane = tid & 31, w = tid >> 5;
    int g = lane >> 2, t = lane & 3;
    int s = blockIdx.x, b = blockIdx.z;
    int t0 = blockIdx.y * 64;
    int mrow = w * 16;
    int r0 = t0 + mrow + g, r1 = r0 + 8;

    const float* s0 = g_score + ((size_t)b * TT + r0) * TT;
    const float* s1 = g_score + ((size_t)b * TT + r1) * TT;
    const float* a0p = adj + (((size_t)b * SS + s) * TT + r0) * TT;
    const float* a1p = adj + (((size_t)b * SS + s) * TT + r1) * TT;
    const float4* gv4 = reinterpret_cast<const float4*>(g_v + (size_t)b * TT * HSZ);
    const float4* sv4 = reinterpret_cast<const float4*>(sv);
    unsigned svb = (unsigned)__cvta_generic_to_shared(sv);

    float acc[16][4];
#pragma unroll
    for (int e = 0; e < 16; e++) {
        acc[e][0] = 0.f; acc[e][1] = 0.f; acc[e][2] = 0.f; acc[e][3] = 0.f;
    }
    float l0 = 0.f, l1 = 0.f;

    // prologue: V chunk 0 -> buffer 0 (permuted row placement)
    for (int f = tid; f < 2048; f += 128) {
        int u = f >> 5, c16 = f & 31;
        int rho = (u & 32) + ((u & 7) << 2) + ((u >> 3) & 3);
        cp_async16(svb + (unsigned)((rho * 33 + c16) << 4), gv4 + (size_t)u * 32 + c16);
    }
    asm volatile("cp.async.commit_group;" ::: "memory");

    // prologue: sub-chunk 0 score/adj -> registers
    int cb0 = 8 * t;
    float4 xs0a = *reinterpret_cast<const float4*>(s0 + cb0);
    float4 xs0b = *reinterpret_cast<const float4*>(s0 + cb0 + 4);
    float4 xs1a = *reinterpret_cast<const float4*>(s1 + cb0);
    float4 xs1b = *reinterpret_cast<const float4*>(s1 + cb0 + 4);
    float4 ya0a = *reinterpret_cast<const float4*>(a0p + cb0);
    float4 ya0b = *reinterpret_cast<const float4*>(a0p + cb0 + 4);
    float4 ya1a = *reinterpret_cast<const float4*>(a1p + cb0);
    float4 ya1b = *reinterpret_cast<const float4*>(a1p + cb0 + 4);

    for (int ch = 0; ch < 8; ch++) {
        if (ch < 7) {
            unsigned boff = (unsigned)(((ch + 1) & 1) * 33792);
            int ubase = (ch + 1) * 64;
            for (int f = tid; f < 2048; f += 128) {
                int u = f >> 5, c16 = f & 31;
                int rho = (u & 32) + ((u & 7) << 2) + ((u >> 3) & 3);
                cp_async16(svb + boff + (unsigned)((rho * 33 + c16) << 4),
                           gv4 + (size_t)(ubase + u) * 32 + c16);
            }
            asm volatile("cp.async.commit_group;" ::: "memory");
            asm volatile("cp.async.wait_group 1;" ::: "memory");
        } else {
            asm volatile("cp.async.wait_group 0;" ::: "memory");
        }
        __syncthreads();
        const float4* vb = sv4 + (ch & 1) * 2112;

#pragma unroll
        for (int sh = 0; sh < 2; sh++) {
            int sc = ch * 2 + sh;
            // exp from prefetched registers (no memory wait)
            float w0[8], w1[8];
            w0[0] = __expf(xs0a.x * ya0a.x); w0[1] = __expf(xs0a.y * ya0a.y);
            w0[2] = __expf(xs0a.z * ya0a.z); w0[3] = __expf(xs0a.w * ya0a.w);
            w0[4] = __expf(xs0b.x * ya0b.x); w0[5] = __expf(xs0b.y * ya0b.y);
            w0[6] = __expf(xs0b.z * ya0b.z); w0[7] = __expf(xs0b.w * ya0b.w);
            w1[0] = __expf(xs1a.x * ya1a.x); w1[1] = __expf(xs1a.y * ya1a.y);
            w1[2] = __expf(xs1a.z * ya1a.z); w1[3] = __expf(xs1a.w * ya1a.w);
            w1[4] = __expf(xs1b.x * ya1b.x); w1[5] = __expf(xs1b.y * ya1b.y);
            w1[6] = __expf(xs1b.z * ya1b.z); w1[7] = __expf(xs1b.w * ya1b.w);
            l0 += ((w0[0] + w0[1]) + (w0[2] + w0[3])) + ((w0[4] + w0[5]) + (w0[6] + w0[7]));
            l1 += ((w1[0] + w1[1]) + (w1[2] + w1[3])) + ((w1[4] + w1[5]) + (w1[6] + w1[7]));
            // prefetch next sub-chunk's score/adj (overlaps with MMA below)
            if (sh == 0 || ch < 7) {
                int cbn = ((sc + 1) >> 1) * 64 + ((sc + 1) & 1) * 32 + 8 * t;
                xs0a = *reinterpret_cast<const float4*>(s0 + cbn);
                xs0b = *reinterpret_cast<const float4*>(s0 + cbn + 4);
                xs1a = *reinterpret_cast<const float4*>(s1 + cbn);
                xs1b = *reinterpret_cast<const float4*>(s1 + cbn + 4);
                ya0a = *reinterpret_cast<const float4*>(a0p + cbn);
                ya0b = *reinterpret_cast<const float4*>(a0p + cbn + 4);
                ya1a = *reinterpret_cast<const float4*>(a1p + cbn);
                ya1b = *reinterpret_cast<const float4*>(a1p + cbn + 4);
            }
            // P @ V MMA section (LDS.128 conflict-free, covers the LDGs above)
#pragma unroll
            for (int kk = 0; kk < 4; kk++) {
                int rlo = sh * 32 + kk * 4 + t;
                const float4* plo = vb + rlo * 33 + 4 * g;
                const float4* phi = plo + 16 * 33;
                unsigned p0 = f2tf(w0[kk]);
                unsigned p1 = f2tf(w1[kk]);
                unsigned p2 = f2tf(w0[4 + kk]);
                unsigned p3 = f2tf(w1[4 + kk]);
#pragma unroll
                for (int j = 0; j < 4; j++) {
                    float4 bl = plo[j];
                    float4 bh = phi[j];
                    int e = 4 * j;
                    mma_tf32(acc[e][0], acc[e][1], acc[e][2], acc[e][3], p0, p1, p2, p3,
                             __float_as_uint(bl.x), __float_as_uint(bh.x));
                    mma_tf32(acc[e + 1][0], acc[e + 1][1], acc[e + 1][2], acc[e + 1][3],
                             p0, p1, p2, p3, __float_as_uint(bl.y), __float_as_uint(bh.y));
                    mma_tf32(acc[e + 2][0], acc[e + 2][1], acc[e + 2][2], acc[e + 2][3],
                             p0, p1, p2, p3, __float_as_uint(bl.z), __float_as_uint(bh.z));
                    mma_tf32(acc[e + 3][0], acc[e + 3][1], acc[e + 3][2], acc[e + 3][3],
                             p0, p1, p2, p3, __float_as_uint(bl.w), __float_as_uint(bh.w));
                }
            }
        }
        __syncthreads();
    }

    // epilogue: quad-reduce row sums over t lanes, normalize, store
    l0 += __shfl_xor_sync(0xffffffffu, l0, 1);
    l0 += __shfl_xor_sync(0xffffffffu, l0, 2);
    l1 += __shfl_xor_sync(0xffffffffu, l1, 1);
    l1 += __shfl_xor_sync(0xffffffffu, l1, 2);
    float rl0 = 1.f / l0, rl1 = 1.f / l1;

    float* ob0 = out + (((size_t)b * SS + s) * TT + r0) * HSZ;
    float* ob1 = out + (((size_t)b * SS + s) * TT + r1) * HSZ;
#pragma unroll
    for (int e = 0; e < 16; e++) {
        int c = 8 * e + 2 * t;
        *reinterpret_cast<float2*>(&ob0[c]) = make_float2(acc[e][0] * rl0, acc[e][1] * rl0);
        *reinterpret_cast<float2*>(&ob1[c]) = make_float2(acc[e][2] * rl1, acc[e][3] * rl1);
    }
}

// ---------------------------------------------------------------------------
extern "C" void kernel_launch(void* const* d_in, const int* in_sizes, int n_in,
                              void* d_out, int out_size) {
    const float* x   = (const float*)d_in[0];
    const float* adj = (const float*)d_in[1];
    const float* Wq  = (const float*)d_in[2];
    const float* Wk  = (const float*)d_in[3];
    const float* Wv  = (const float*)d_in[4];
    float* out = (float*)d_out;

    const int smem_k1 = 128 * 132 * 4;     // 67584
    const int smem_k2a = 64 * 132 * 4;     // 33792
    const int smem_k2b = 64 * 144 * 4;     // 36864
    const int smem_k3 = 2 * 64 * 33 * 16;  // 67584 (double-buffered permuted V)

    cudaFuncSetAttribute(k_wqwk, cudaFuncAttributeMaxDynamicSharedMemorySize, smem_k1);
    cudaFuncSetAttribute(k_yv, cudaFuncAttributeMaxDynamicSharedMemorySize, smem_k2a);
    cudaFuncSetAttribute(k_score, cudaFuncAttributeMaxDynamicSharedMemorySize, smem_k2b);
    cudaFuncSetAttribute(k_attn, cudaFuncAttributeMaxDynamicSharedMemorySize, smem_k3);

    k_wqwk<<<128, 128, smem_k1>>>(Wq, Wk);
    k_yv<<<(BB * TT) / 64, 128, smem_k2a>>>(x, Wv);
    k_score<<<dim3(TT / 64, TT / 64, BB), 128, smem_k2b>>>(x);
    k_attn<<<dim3(SS, TT / 64, BB), 128, smem_k3>>>(adj, out);
}

// round 17
// speedup vs baseline: 1.8315x; 1.0065x over previous
#include <cuda_runtime.h>
#include <cstdint>
#include <cstddef>

// Problem constants
#define BB 32
#define SS 8
#define TT 512
#define CC 128
#define HSZ 128

// Scratch (device globals; no runtime allocation allowed)
__device__ float g_M[CC * CC];                       // Wq @ Wk^T, tf32-rounded
__device__ float g_yp[BB * TT * CC];                 // x @ M, tf32, COLUMN-PERMUTED: h -> (h&7)*16 + (h>>3)
__device__ float g_v[BB * TT * HSZ];                 // x @ Wv, tf32, COLUMN-PERMUTED (same map)
__device__ float g_xp[(size_t)BB * TT * 144];        // x tf32 in k_score smem layout: row*144 + j*36 + c4  (c = 4*c4+j)
__device__ float g_score[(size_t)BB * TT * TT];      // fp32 scores (33.5 MB)

__device__ __forceinline__ unsigned f2tf(float x) {
    unsigned u;
    asm("cvt.rna.tf32.f32 %0, %1;" : "=r"(u) : "f"(x));
    return u;
}
__device__ __forceinline__ float f2tf_f(float x) { return __uint_as_float(f2tf(x)); }

__device__ __forceinline__ void mma_tf32(float& c0, float& c1, float& c2, float& c3,
                                         unsigned a0, unsigned a1, unsigned a2, unsigned a3,
                                         unsigned b0, unsigned b1) {
    asm volatile(
        "mma.sync.aligned.m16n8k8.row.col.f32.tf32.tf32.f32 "
        "{%0,%1,%2,%3},{%4,%5,%6,%7},{%8,%9},{%0,%1,%2,%3};\n"
        : "+f"(c0), "+f"(c1), "+f"(c2), "+f"(c3)
        : "r"(a0), "r"(a1), "r"(a2), "r"(a3), "r"(b0), "r"(b1));
}

__device__ __forceinline__ void cp_async16(unsigned dst, const void* src) {
    asm volatile("cp.async.cg.shared.global [%0], [%1], 16;" :: "r"(dst), "l"(src) : "memory");
}

// ---------------------------------------------------------------------------
// K1: M = Wq @ Wk^T  (fp32 FFMA, rounded to tf32 on store)
// ---------------------------------------------------------------------------
__global__ void k_wqwk(const float* __restrict__ Wq, const float* __restrict__ Wk) {
    extern __shared__ float sm[];  // sWk[128][132]
    int tid = threadIdx.x;
    int c1 = blockIdx.x;
    for (int i = tid; i < CC * CC; i += 128) {
        sm[(i >> 7) * 132 + (i & 127)] = Wk[i];
    }
    __syncthreads();
    const float* wqr = Wq + c1 * CC;
    float acc = 0.f;
#pragma unroll 8
    for (int h = 0; h < CC; h++) acc += wqr[h] * sm[tid * 132 + h];
    g_M[c1 * CC + tid] = f2tf_f(acc);
}

// ---------------------------------------------------------------------------
// K2a: y = x @ M (permuted -> g_yp),  v = x @ Wv (permuted -> g_v),
// plus x tf32 re-layout -> g_xp (k_score B staging, 144-stride rows).
// grid(B*T/64), block(128), dyn smem = 64*132*4
// ---------------------------------------------------------------------------
__global__ void __launch_bounds__(128) k_yv(const float* __restrict__ x,
                                            const float* __restrict__ Wv) {
    extern __shared__ float sm[];  // sx[64][132] tf32-rounded
    int tid = threadIdx.x;
    int row0 = blockIdx.x * 64;
    for (int f = tid; f < 64 * CC / 4; f += 128) {
        int r = f >> 5, c4 = f & 31;
        float4 v4 = *reinterpret_cast<const float4*>(&x[(size_t)(row0 + r) * CC + c4 * 4]);
        float4 o;
        o.x = f2tf_f(v4.x); o.y = f2tf_f(v4.y); o.z = f2tf_f(v4.z); o.w = f2tf_f(v4.w);
        *reinterpret_cast<float4*>(&sm[r * 132 + c4 * 4]) = o;
        // g_xp: element c=4*c4+j at row*144 + j*36 + c4 (coalesced per j)
        float* xr = g_xp + (size_t)(row0 + r) * 144 + c4;
        xr[0]   = o.x;
        xr[36]  = o.y;
        xr[72]  = o.z;
        xr[108] = o.w;
    }
    __syncthreads();
    int lane = tid & 31, w = tid >> 5;
    int gid = lane >> 2, tig = lane & 3;
    int mrow = w * 16;
    for (int nt = 0; nt < 32; nt++) {
        bool isv = nt >= 16;
        const float* Bsrc = isv ? Wv : g_M;
        int nt8 = nt & 15;
        int n = nt8 * 8;
        float c0 = 0, c1 = 0, c2 = 0, c3 = 0;
#pragma unroll
        for (int kk = 0; kk < 16; kk++) {
            int k = kk * 8;
            unsigned a0 = __float_as_uint(sm[(mrow + gid) * 132 + k + tig]);
            unsigned a1 = __float_as_uint(sm[(mrow + gid + 8) * 132 + k + tig]);
            unsigned a2 = __float_as_uint(sm[(mrow + gid) * 132 + k + tig + 4]);
            unsigned a3 = __float_as_uint(sm[(mrow + gid + 8) * 132 + k + tig + 4]);
            float bv0 = Bsrc[(k + tig) * CC + n + gid];
            float bv1 = Bsrc[(k + tig + 4) * CC + n + gid];
            unsigned b0 = isv ? f2tf(bv0) : __float_as_uint(bv0);
            unsigned b1 = isv ? f2tf(bv1) : __float_as_uint(bv1);
            mma_tf32(c0, c1, c2, c3, a0, a1, a2, a3, b0, b1);
        }
        int r0 = row0 + mrow + gid;
        // permuted store: col h -> (h&7)*16 + (h>>3); h = n+2*tig
        float* dst = isv ? g_v : g_yp;
        int col0 = 32 * tig + nt8;
        dst[(size_t)r0 * HSZ + col0]            = f2tf_f(c0);
        dst[(size_t)r0 * HSZ + col0 + 16]       = f2tf_f(c1);
        dst[(size_t)(r0 + 8) * HSZ + col0]      = f2tf_f(c2);
        dst[(size_t)(r0 + 8) * HSZ + col0 + 16] = f2tf_f(c3);
    }
}

// ---------------------------------------------------------------------------
// K2b: score[b,t,u] = (y[b,t,:] . x[b,u,:]) * C^-0.5
// B tile: straight cp.async of pre-laid-out g_xp (no cvt/STS, conflict-free).
// A fragments: 16 LDG.128 from permuted g_yp (pos 16t+kk <-> h=8kk+t).
// grid(8, 8, 32) = (t_tile, u_chunk, b), block(128), dyn smem = 64*144*4
// ---------------------------------------------------------------------------
__global__ void __launch_bounds__(128) k_score(int dummy) {
    extern __shared__ float sxp[];  // [64][144]
    int tid = threadIdx.x;
    int lane = tid & 31, w = tid >> 5, g = lane >> 2, t = lane & 3;
    int b = blockIdx.z;
    int t0 = blockIdx.x * 64;
    int u0 = blockIdx.y * 64;
    int mrow = w * 16;
    int R0 = t0 + mrow + g, R1 = R0 + 8;
    const float scl = 0.08838834764831843f;  // 128^-0.5
    unsigned sb = (unsigned)__cvta_generic_to_shared(sxp);

    // B tile: 2304 x 16B contiguous cp.async (includes unread pad slots)
    const float* xpb = g_xp + (size_t)(b * TT + u0) * 144;
    for (int f = tid; f < 64 * 36; f += 128) {
        cp_async16(sb + (unsigned)(f * 16), xpb + f * 4);
    }
    asm volatile("cp.async.commit_group;" ::: "memory");

    // A fragments: 16 LDG.128 (overlap cp.async arrival)
    const float4* yp0 = reinterpret_cast<const float4*>(g_yp + (size_t)(b * TT + R0) * CC);
    const float4* yp1 = reinterpret_cast<const float4*>(g_yp + (size_t)(b * TT + R1) * CC);
    float af0[16], af1[16], af2[16], af3[16];
#pragma unroll
    for (int q = 0; q < 4; q++) {
        *reinterpret_cast<float4*>(&af0[4 * q]) = yp0[4 * t + q];
        *reinterpret_cast<float4*>(&af1[4 * q]) = yp1[4 * t + q];
        *reinterpret_cast<float4*>(&af2[4 * q]) = yp0[4 * (t + 4) + q];
        *reinterpret_cast<float4*>(&af3[4 * q]) = yp1[4 * (t + 4) + q];
    }
    asm volatile("cp.async.wait_group 0;" ::: "memory");
    __syncthreads();

#pragma unroll
    for (int nt = 0; nt < 8; nt++) {
        int brow = nt * 8 + g;
        const float4* bp = reinterpret_cast<const float4*>(&sxp[brow * 144 + t * 36]);
        float c0 = 0, c1 = 0, c2 = 0, c3 = 0;
#pragma unroll
        for (int j = 0; j < 8; j++) {
            float4 bq = bp[j];  // K pairs for kk=2j, 2j+1
            mma_tf32(c0, c1, c2, c3,
                     __float_as_uint(af0[2 * j]), __float_as_uint(af1[2 * j]),
                     __float_as_uint(af2[2 * j]), __float_as_uint(af3[2 * j]),
                     __float_as_uint(bq.x), __float_as_uint(bq.y));
            mma_tf32(c0, c1, c2, c3,
                     __float_as_uint(af0[2 * j + 1]), __float_as_uint(af1[2 * j + 1]),
                     __float_as_uint(af2[2 * j + 1]), __float_as_uint(af3[2 * j + 1]),
                     __float_as_uint(bq.z), __float_as_uint(bq.w));
        }
        float* d0 = g_score + ((size_t)b * TT + R0) * TT + u0 + nt * 8;
        float* d1 = g_score + ((size_t)b * TT + R1) * TT + u0 + nt * 8;
        *reinterpret_cast<float2*>(&d0[2 * t]) = make_float2(c0 * scl, c1 * scl);
        *reinterpret_cast<float2*>(&d1[2 * t]) = make_float2(c2 * scl, c3 * scl);
    }
}

// ---------------------------------------------------------------------------
// K3: softmax + P@V, tf32 mma — UNCHANGED from R16 (144.9 us, proven).
// Register-pipelined score/adj gathers; permuted-V conflict-free LDS.128;
// cp.async double-buffered V; no max subtraction.
// grid(8, 8, 32) = (s, t_tile, b); dyn smem = 2*64*33*16 = 67584
// ---------------------------------------------------------------------------
__global__ void __launch_bounds__(128, 3) k_attn(const float* __restrict__ adj,
                                                 float* __restrict__ out) {
    extern __shared__ float sv[];
    int tid = threadIdx.x, lane = tid & 31, w = tid >> 5;
    int g = lane >> 2, t = lane & 3;
    int s = blockIdx.x, b = blockIdx.z;
    int t0 = blockIdx.y * 64;
    int mrow = w * 16;
    int r0 = t0 + mrow + g, r1 = r0 + 8;

    const float* s0 = g_score + ((size_t)b * TT + r0) * TT;
    const float* s1 = g_score + ((size_t)b * TT + r1) * TT;
    const float* a0p = adj + (((size_t)b * SS + s) * TT + r0) * TT;
    const float* a1p = adj + (((size_t)b * SS + s) * TT + r1) * TT;
    const float4* gv4 = reinterpret_cast<const float4*>(g_v + (size_t)b * TT * HSZ);
    const float4* sv4 = reinterpret_cast<const float4*>(sv);
    unsigned svb = (unsigned)__cvta_generic_to_shared(sv);

    float acc[16][4];
#pragma unroll
    for (int e = 0; e < 16; e++) {
        acc[e][0] = 0.f; acc[e][1] = 0.f; acc[e][2] = 0.f; acc[e][3] = 0.f;
    }
    float l0 = 0.f, l1 = 0.f;

    // prologue: V chunk 0 -> buffer 0 (permuted row placement)
    for (int f = tid; f < 2048; f += 128) {
        int u = f >> 5, c16 = f & 31;
        int rho = (u & 32) + ((u & 7) << 2) + ((u >> 3) & 3);
        cp_async16(svb + (unsigned)((rho * 33 + c16) << 4), gv4 + (size_t)u * 32 + c16);
    }
    asm volatile("cp.async.commit_group;" ::: "memory");

    // prologue: sub-chunk 0 score/adj -> registers
    int cb0 = 8 * t;
    float4 xs0a = *reinterpret_cast<const float4*>(s0 + cb0);
    float4 xs0b = *reinterpret_cast<const float4*>(s0 + cb0 + 4);
    float4 xs1a = *reinterpret_cast<const float4*>(s1 + cb0);
    float4 xs1b = *reinterpret_cast<const float4*>(s1 + cb0 + 4);
    float4 ya0a = *reinterpret_cast<const float4*>(a0p + cb0);
    float4 ya0b = *reinterpret_cast<const float4*>(a0p + cb0 + 4);
    float4 ya1a = *reinterpret_cast<const float4*>(a1p + cb0);
    float4 ya1b = *reinterpret_cast<const float4*>(a1p + cb0 + 4);

    for (int ch = 0; ch < 8; ch++) {
        if (ch < 7) {
            unsigned boff = (unsigned)(((ch + 1) & 1) * 33792);
            int ubase = (ch + 1) * 64;
            for (int f = tid; f < 2048; f += 128) {
                int u = f >> 5, c16 = f & 31;
                int rho = (u & 32) + ((u & 7) << 2) + ((u >> 3) & 3);
                cp_async16(svb + boff + (unsigned)((rho * 33 + c16) << 4),
                           gv4 + (size_t)(ubase + u) * 32 + c16);
            }
            asm volatile("cp.async.commit_group;" ::: "memory");
            asm volatile("cp.async.wait_group 1;" ::: "memory");
        } else {
            asm volatile("cp.async.wait_group 0;" ::: "memory");
        }
        __syncthreads();
        const float4* vb = sv4 + (ch & 1) * 2112;

#pragma unroll
        for (int sh = 0; sh < 2; sh++) {
            int sc = ch * 2 + sh;
            float w0[8], w1[8];
            w0[0] = __expf(xs0a.x * ya0a.x); w0[1] = __expf(xs0a.y * ya0a.y);
            w0[2] = __expf(xs0a.z * ya0a.z); w0[3] = __expf(xs0a.w * ya0a.w);
            w0[4] = __expf(xs0b.x * ya0b.x); w0[5] = __expf(xs0b.y * ya0b.y);
            w0[6] = __expf(xs0b.z * ya0b.z); w0[7] = __expf(xs0b.w * ya0b.w);
            w1[0] = __expf(xs1a.x * ya1a.x); w1[1] = __expf(xs1a.y * ya1a.y);
            w1[2] = __expf(xs1a.z * ya1a.z); w1[3] = __expf(xs1a.w * ya1a.w);
            w1[4] = __expf(xs1b.x * ya1b.x); w1[5] = __expf(xs1b.y * ya1b.y);
            w1[6] = __expf(xs1b.z * ya1b.z); w1[7] = __expf(xs1b.w * ya1b.w);
            l0 += ((w0[0] + w0[1]) + (w0[2] + w0[3])) + ((w0[4] + w0[5]) + (w0[6] + w0[7]));
            l1 += ((w1[0] + w1[1]) + (w1[2] + w1[3])) + ((w1[4] + w1[5]) + (w1[6] + w1[7]));
            if (sh == 0 || ch < 7) {
                int cbn = ((sc + 1) >> 1) * 64 + ((sc + 1) & 1) * 32 + 8 * t;
                xs0a = *reinterpret_cast<const float4*>(s0 + cbn);
                xs0b = *reinterpret_cast<const float4*>(s0 + cbn + 4);
                xs1a = *reinterpret_cast<const float4*>(s1 + cbn);
                xs1b = *reinterpret_cast<const float4*>(s1 + cbn + 4);
                ya0a = *reinterpret_cast<const float4*>(a0p + cbn);
                ya0b = *reinterpret_cast<const float4*>(a0p + cbn + 4);
                ya1a = *reinterpret_cast<const float4*>(a1p + cbn);
                ya1b = *reinterpret_cast<const float4*>(a1p + cbn + 4);
            }
#pragma unroll
            for (int kk = 0; kk < 4; kk++) {
                int rlo = sh * 32 + kk * 4 + t;
                const float4* plo = vb + rlo * 33 + 4 * g;
                const float4* phi = plo + 16 * 33;
                unsigned p0 = f2tf(w0[kk]);
                unsigned p1 = f2tf(w1[kk]);
                unsigned p2 = f2tf(w0[4 + kk]);
                unsigned p3 = f2tf(w1[4 + kk]);
#pragma unroll
                for (int j = 0; j < 4; j++) {
                    float4 bl = plo[j];
                    float4 bh = phi[j];
                    int e = 4 * j;
                    mma_tf32(acc[e][0], acc[e][1], acc[e][2], acc[e][3], p0, p1, p2, p3,
                             __float_as_uint(bl.x), __float_as_uint(bh.x));
                    mma_tf32(acc[e + 1][0], acc[e + 1][1], acc[e + 1][2], acc[e + 1][3],
                             p0, p1, p2, p3, __float_as_uint(bl.y), __float_as_uint(bh.y));
                    mma_tf32(acc[e + 2][0], acc[e + 2][1], acc[e + 2][2], acc[e + 2][3],
                             p0, p1, p2, p3, __float_as_uint(bl.z), __float_as_uint(bh.z));
                    mma_tf32(acc[e + 3][0], acc[e + 3][1], acc[e + 3][2], acc[e + 3][3],
                             p0, p1, p2, p3, __float_as_uint(bl.w), __float_as_uint(bh.w));
                }
            }
        }
        __syncthreads();
    }

    l0 += __shfl_xor_sync(0xffffffffu, l0, 1);
    l0 += __shfl_xor_sync(0xffffffffu, l0, 2);
    l1 += __shfl_xor_sync(0xffffffffu, l1, 1);
    l1 += __shfl_xor_sync(0xffffffffu, l1, 2);
    float rl0 = 1.f / l0, rl1 = 1.f / l1;

    float* ob0 = out + (((size_t)b * SS + s) * TT + r0) * HSZ;
    float* ob1 = out + (((size_t)b * SS + s) * TT + r1) * HSZ;
#pragma unroll
    for (int e = 0; e < 16; e++) {
        int c = 8 * e + 2 * t;
        *reinterpret_cast<float2*>(&ob0[c]) = make_float2(acc[e][0] * rl0, acc[e][1] * rl0);
        *reinterpret_cast<float2*>(&ob1[c]) = make_float2(acc[e][2] * rl1, acc[e][3] * rl1);
    }
}

// ---------------------------------------------------------------------------
extern "C" void kernel_launch(void* const* d_in, const int* in_sizes, int n_in,
                              void* d_out, int out_size) {
    const float* x   = (const float*)d_in[0];
    const float* adj = (const float*)d_in[1];
    const float* Wq  = (const float*)d_in[2];
    const float* Wk  = (const float*)d_in[3];
    const float* Wv  = (const float*)d_in[4];
    float* out = (float*)d_out;

    const int smem_k1 = 128 * 132 * 4;     // 67584
    const int smem_k2a = 64 * 132 * 4;     // 33792
    const int smem_k2b = 64 * 144 * 4;     // 36864
    const int smem_k3 = 2 * 64 * 33 * 16;  // 67584

    cudaFuncSetAttribute(k_wqwk, cudaFuncAttributeMaxDynamicSharedMemorySize, smem_k1);
    cudaFuncSetAttribute(k_yv, cudaFuncAttributeMaxDynamicSharedMemorySize, smem_k2a);
    cudaFuncSetAttribute(k_score, cudaFuncAttributeMaxDynamicSharedMemorySize, smem_k2b);
    cudaFuncSetAttribute(k_attn, cudaFuncAttributeMaxDynamicSharedMemorySize, smem_k3);

    k_wqwk<<<128, 128, smem_k1>>>(Wq, Wk);
    k_yv<<<(BB * TT) / 64, 128, smem_k2a>>>(x, Wv);
    k_score<<<dim3(TT / 64, TT / 64, BB), 128, smem_k2b>>>(0);
    k_attn<<<dim3(SS, TT / 64, BB), 128, smem_k3>>>(adj, out);
}